// round 14
// baseline (speedup 1.0000x reference)
#include <cuda_runtime.h>
#include <math.h>

#define NCOLS 3872
#define NROWS 32768
#define NG8   (NROWS / 8)
#define NG16  (NROWS / 16)
#define GRID_P 296
#define GRID_R 444
#define GRID_G 444
#define NDV 3360            // 120 pairs * 28 (14 sum + 14 sumsq)
#define NRV 2192            // non-dist columns
#define CHUNK 37
#define NCH_D 8                // dist chunks  (8  * 37 = 296)
#define NCH_R 12               // rest chunks  (12 * 37 = 444)
#define SEL_NB 64              // blocks in fused select kernel
#define SEL_W1 (NCH_D * NDV)            // 26880 dist work items
#define SEL_W  (SEL_W1 + NCH_R * 2 * NRV) // + 52608 rest = 79488

__device__ float  g_scr_d[GRID_P * NDV];
__device__ float  g_scr_r[GRID_R * NRV * 2];
__device__ double g_psum[NCH_R * 4096];
__device__ double g_psumsq[NCH_R * 4096];
__device__ unsigned long long g_key[4096];
__device__ int    g_rank[4096];
__device__ int    g_sel_desc[512];
__device__ int    g_sel_j[512];
__device__ unsigned g_bar;

__device__ __forceinline__ float frcp(float x) {
    float r; asm("rcp.approx.f32 %0, %1;" : "=f"(r) : "f"(x)); return r;
}
__device__ __forceinline__ float fsqrt_a(float x) {
    float r; asm("sqrt.approx.f32 %0, %1;" : "=f"(r) : "f"(x)); return r;
}

// multi-use grid barrier: monotonic ticket counter, works across graph replays
__device__ __forceinline__ void grid_barrier() {
    __syncthreads();
    if (threadIdx.x == 0) {
        __threadfence();
        unsigned v = atomicAdd(&g_bar, 1u) + 1u;
        unsigned target = ((v - 1u) / SEL_NB + 1u) * SEL_NB;
        unsigned cur;
        do {
            asm volatile("ld.acquire.gpu.u32 %0, [%1];" : "=r"(cur) : "l"(&g_bar));
        } while (cur < target);
    }
    __syncthreads();
}

__device__ __forceinline__ void triu_pair(int p, int n, int &i, int &j) {
    int ii = 0, rem = p, cnt = n - 1;
    while (rem >= cnt) { rem -= cnt; cnt--; ii++; }
    i = ii; j = ii + 1 + rem;
}

// Column descriptor: kind<<24 | a<<12 | b
__device__ __forceinline__ int decode(int c) {
    int kind, a, b = 0;
    if (c < 128)       { kind = 0; a = c; }
    else if (c < 1808) { int q = c - 128; kind = 16 + q / 120; a = q % 120; }
    else if (c < 1936) { kind = 1; a = c - 1808; }
    else if (c < 2064) { kind = 2; a = c - 1936; }
    else if (c < 2192) { kind = 3; a = c - 2064; }
    else if (c < 2320) { kind = 4; a = c - 2192; }
    else if (c < 2448) { kind = 5; a = c - 2320; }
    else if (c < 2464) { kind = 6; a = (c - 2448) * 8; }
    else if (c < 2912) {
        int idx = c - 2464; int n = idx / 28, pr = idx % 28;
        int i, j; triu_pair(pr, 8, i, j);
        kind = 7; a = n * 8 + i; b = n * 8 + j;
    } else {
        int idx = c - 2912; int pr = idx / 8, k = idx % 8;
        int i, j; triu_pair(pr, 16, i, j);
        kind = 7; a = i * 8 + k; b = j * 8 + k;
    }
    return (kind << 24) | (a << 12) | b;
}

// distance power chain: accumulate 14 values + squares for distance d
__device__ __forceinline__ void dchain(float d, float acc[28]) {
    float dpe = d + 1e-3f;
    float r1 = frcp(dpe);
    float d2 = d * d, d3 = d2 * d, d4 = d2 * d2, d6 = d3 * d3, d8 = d4 * d4;
    float v[14];
    v[0] = d;
    v[1] = r1;
    v[2] = frcp(d2 + 1e-3f);
    v[3] = frcp(d3 + 1e-3f);
    v[4] = frcp(d4 + 1e-3f);
    v[5] = frcp(d4 * d + 1e-3f);
    v[6] = frcp(d6 + 1e-3f);
    v[7] = frcp(d8 + 1e-3f);
    v[8] = frcp(d8 * d2 + 1e-3f);
    v[9] = frcp(d6 * d6 + 1e-3f);
    v[10] = frcp(d8 * d6 + 1e-3f);
    float e = __expf(-d);
    v[11] = e;
    v[12] = e * r1;
    v[13] = __logf(dpe);
    #pragma unroll
    for (int k = 0; k < 14; k++) {
        acc[k] += v[k];
        acc[14 + k] = fmaf(v[k], v[k], acc[14 + k]);
    }
}

__device__ __forceinline__ float pbc_dist(const float* zp, int bi, int bj) {
    float dx = zp[2 * bi]     - zp[2 * bj];
    float dy = zp[2 * bi + 1] - zp[2 * bj + 1];
    dx -= 10.0f * rintf(dx * 0.1f);
    dy -= 10.0f * rintf(dy * 0.1f);
    return fsqrt_a(dx * dx + dy * dy) + 1e-6f;
}

// accumulate 16 rows for one non-dist column; switch hoisted out of row loop
__device__ __forceinline__ void acc16(int desc, const float (*zn)[128],
                                      float &fs, float &fq) {
    const int kind = desc >> 24;
    const int a = (desc >> 12) & 0xFFF;
    const int b = desc & 0xFFF;
    switch (kind) {
        case 0:
            #pragma unroll
            for (int r = 0; r < 16; r++) { float v = zn[r][a]; fs += v; fq = fmaf(v, v, fq); }
            break;
        case 1:
            #pragma unroll
            for (int r = 0; r < 16; r++) { float t = zn[r][a]; float v = t * t; fs += v; fq = fmaf(v, v, fq); }
            break;
        case 2:
            #pragma unroll
            for (int r = 0; r < 16; r++) { float v = __sinf(zn[r][a]); fs += v; fq = fmaf(v, v, fq); }
            break;
        case 3:
            #pragma unroll
            for (int r = 0; r < 16; r++) { float v = __cosf(zn[r][a]); fs += v; fq = fmaf(v, v, fq); }
            break;
        case 4:
            #pragma unroll
            for (int r = 0; r < 16; r++) { float v = __logf(fabsf(zn[r][a]) + 1e-3f); fs += v; fq = fmaf(v, v, fq); }
            break;
        case 5:
            #pragma unroll
            for (int r = 0; r < 16; r++) { float v = __expf(fminf(fmaxf(zn[r][a], -10.0f), 2.0f)); fs += v; fq = fmaf(v, v, fq); }
            break;
        case 6:
            #pragma unroll
            for (int r = 0; r < 16; r++) {
                float s = 0.0f;
                #pragma unroll
                for (int k = 4; k < 8; k++) { float t = zn[r][a + k]; s += t * t; }
                fs += s; fq = fmaf(s, s, fq);
            }
            break;
        default:
            #pragma unroll
            for (int r = 0; r < 16; r++) { float v = zn[r][a] * zn[r][b]; fs += v; fq = fmaf(v, v, fq); }
            break;
    }
}

// ---------------- pass 1a: distance columns (16 rows/iter, float2 coords) --
__global__ void __launch_bounds__(512, 2)
p1dist_kernel(const float* __restrict__ z_flat) {
    __shared__ float s_zp[16][32];
    __shared__ float s_red[NDV];
    const int tid = threadIdx.x;
    const int bid = blockIdx.x;
    const int lrow = tid >> 4;       // valid for tid<256: 0..15
    const int lnode = tid & 15;
    const int bp = tid % 120, br = tid / 120;
    int bi = 0, bj = 0;
    if (tid < 480) triu_pair(bp, 16, bi, bj);

    float acc[28];
    #pragma unroll
    for (int k = 0; k < 28; k++) acc[k] = 0.f;

    float2 zc = make_float2(0.f, 0.f);
    if (tid < 256)
        zc = *(const float2*)&z_flat[(size_t)(bid * 16 + lrow) * 128 + lnode * 8];
    for (int g = bid; g < NG16; g += GRID_P) {
        if (tid < 256) {
            s_zp[lrow][lnode * 2]     = fminf(fmaxf(zc.x, -1e6f), 1e6f);
            s_zp[lrow][lnode * 2 + 1] = fminf(fmaxf(zc.y, -1e6f), 1e6f);
        }
        __syncthreads();
        int gn = g + GRID_P;
        float2 zc_n = make_float2(0.f, 0.f);
        if (tid < 256 && gn < NG16)
            zc_n = *(const float2*)&z_flat[(size_t)(gn * 16 + lrow) * 128 + lnode * 8];
        if (tid < 480) {
            #pragma unroll
            for (int q = 0; q < 4; q++)
                dchain(pbc_dist(s_zp[br + 4 * q], bi, bj), acc);
        }
        __syncthreads();
        zc = zc_n;
    }
    if (tid < 480 && br == 0) {
        #pragma unroll
        for (int k = 0; k < 28; k++) s_red[bp * 28 + k] = acc[k];
    }
    __syncthreads();
    for (int s = 1; s < 4; s++) {
        if (tid < 480 && br == s) {
            #pragma unroll
            for (int k = 0; k < 28; k++) s_red[bp * 28 + k] += acc[k];
        }
        __syncthreads();
    }
    for (int v = tid; v < NDV; v += 512)
        g_scr_d[bid * NDV + v] = s_red[v];
}

// ---------------- pass 1b: non-dist columns (16 rows/iter, 3 CTA/SM) -------
__global__ void __launch_bounds__(512, 3)
p1rest_kernel(const float* __restrict__ z_flat,
              const float* __restrict__ z_mean,
              const float* __restrict__ z_std) {
    __shared__ float s_zn[16][128];
    const int tid = threadIdx.x;
    const int bid = blockIdx.x;
    const int row4 = tid >> 5;        // 0..15
    const int c4 = (tid & 31) * 4;
    const float4 zm4 = *(const float4*)&z_mean[c4];
    float4 zs4 = *(const float4*)&z_std[c4];
    const float4 zi4 = make_float4(frcp(zs4.x), frcp(zs4.y), frcp(zs4.z), frcp(zs4.w));

    int desc[5]; bool val[5];
    #pragma unroll
    for (int k = 0; k < 5; k++) {
        int i = tid + k * 512;
        val[k] = (i < NRV);
        int col = (i < 128) ? i : i + 1680;
        desc[k] = val[k] ? decode(col) : 0;
    }
    float fs[5], fq[5];
    #pragma unroll
    for (int k = 0; k < 5; k++) { fs[k] = 0.f; fq[k] = 0.f; }

    float4 zv = make_float4(0.f, 0.f, 0.f, 0.f);
    if (bid < NG16)
        zv = *(const float4*)&z_flat[(size_t)(bid * 16 + row4) * 128 + c4];
    for (int g = bid; g < NG16; g += GRID_R) {
        {
            float4 w;
            w.x = (fminf(fmaxf(zv.x, -1e6f), 1e6f) - zm4.x) * zi4.x;
            w.y = (fminf(fmaxf(zv.y, -1e6f), 1e6f) - zm4.y) * zi4.y;
            w.z = (fminf(fmaxf(zv.z, -1e6f), 1e6f) - zm4.z) * zi4.z;
            w.w = (fminf(fmaxf(zv.w, -1e6f), 1e6f) - zm4.w) * zi4.w;
            *(float4*)&s_zn[row4][c4] = w;
        }
        __syncthreads();
        int gn = g + GRID_R;
        float4 zv_n = make_float4(0.f, 0.f, 0.f, 0.f);
        if (gn < NG16)
            zv_n = *(const float4*)&z_flat[(size_t)(gn * 16 + row4) * 128 + c4];
        #pragma unroll
        for (int k = 0; k < 5; k++)
            if (val[k]) acc16(desc[k], s_zn, fs[k], fq[k]);
        __syncthreads();
        zv = zv_n;
    }
    #pragma unroll
    for (int k = 0; k < 5; k++) {
        int i = tid + k * 512;
        if (val[k]) {
            g_scr_r[bid * (2 * NRV) + i] = fs[k];
            g_scr_r[bid * (2 * NRV) + NRV + i] = fq[k];
        }
    }
}

// ---------------- fused select: reduce + keys + rank + sel ------------------
__global__ void __launch_bounds__(1024, 1)
select_kernel(const int* __restrict__ feature_mask) {
    __shared__ unsigned long long sk[256];
    __shared__ int s_top[1000];
    __shared__ int s_selcol[512];
    __shared__ unsigned s_skey[512];
    const int tid = threadIdx.x;
    const int tg = blockIdx.x * 1024 + tid;

    // ---- phase 1: chunked f64 reduce (column-ordered output) ----
    for (int w = tg; w < SEL_W; w += SEL_NB * 1024) {
        if (w < SEL_W1) {
            int chunk = w / NDV;
            int v = w - chunk * NDV;
            double s = 0.0;
            int b0 = chunk * CHUNK;
            #pragma unroll 4
            for (int b = b0; b < b0 + CHUNK; b++) s += (double)g_scr_d[b * NDV + v];
            int pair = v / 28, k = v % 28;
            int col = 128 + (k % 14) * 120 + pair;
            if (k < 14) g_psum[chunk * 4096 + col] = s;
            else        g_psumsq[chunk * 4096 + col] = s;
        } else {
            int u = w - SEL_W1;
            int chunk = u / (2 * NRV);
            int i = u - chunk * (2 * NRV);
            double s = 0.0;
            int b0 = chunk * CHUNK;
            #pragma unroll 4
            for (int b = b0; b < b0 + CHUNK; b++) s += (double)g_scr_r[b * (2 * NRV) + i];
            int ii = (i < NRV) ? i : i - NRV;
            int col = (ii < 128) ? ii : ii + 1680;
            if (i < NRV) g_psum[chunk * 4096 + col] = s;
            else         g_psumsq[chunk * 4096 + col] = s;
        }
    }
    grid_barrier();

    // ---- phase 2: keys + zero ranks ----
    if (tg < 4096) {
        g_rank[tg] = 0;
        unsigned long long key = 0ull;
        if (tg < NCOLS) {
            int nch = (tg >= 128 && tg < 1808) ? NCH_D : NCH_R;
            double s = 0.0, qq = 0.0;
            for (int ch = 0; ch < nch; ch++) {
                s  += g_psum[ch * 4096 + tg];
                qq += g_psumsq[ch * 4096 + tg];
            }
            double var = (qq - s * (s * (1.0 / 32768.0))) * (1.0 / 32767.0);
            float fv = (float)var;
            unsigned u = __float_as_uint(fv);
            u = (u & 0x80000000u) ? ~u : (u | 0x80000000u);
            key = ((unsigned long long)u << 32) |
                  (unsigned long long)(0xFFFFFFFFu - (unsigned)tg);
        }
        g_key[tg] = key;
    }
    grid_barrier();

    // ---- phase 3: 2-D tiled rank (4 cand-groups x 16 key-slices) ----
    {
        int cg = blockIdx.x & 3;
        int sl = blockIdx.x >> 2;
        if (tid < 256) sk[tid] = g_key[sl * 256 + tid];
        __syncthreads();
        int c = cg * 1024 + tid;
        unsigned long long mykey = g_key[c];
        int r = 0;
        #pragma unroll 8
        for (int i = 0; i < 256; i++) r += (sk[i] > mykey);
        if (r > 0) atomicAdd(&g_rank[c], r);
    }
    grid_barrier();

    // ---- phase 4: scatter + selection + class sort (block 0) ----
    if (blockIdx.x == 0) {
        #pragma unroll
        for (int k = 0; k < 4; k++) {
            int c = tid + k * 1024;
            if (c < NCOLS) {
                int r = g_rank[c];
                if (r < 1000) s_top[r] = c;
            }
        }
        __syncthreads();
        if (tid < 512) {
            int colid = s_top[feature_mask[tid]];
            s_selcol[tid] = colid;
            unsigned cls = (unsigned)(decode(colid) >> 24);
            s_skey[tid] = (cls << 16) | (unsigned)tid;
        }
        __syncthreads();
        for (int k = 2; k <= 512; k <<= 1) {
            for (int j = k >> 1; j > 0; j >>= 1) {
                if (tid < 512) {
                    int ixj = tid ^ j;
                    if (ixj > tid) {
                        unsigned a = s_skey[tid], b = s_skey[ixj];
                        bool up = ((tid & k) == 0);
                        if (up ? (a > b) : (a < b)) { s_skey[tid] = b; s_skey[ixj] = a; }
                    }
                }
                __syncthreads();
            }
        }
        if (tid < 512) {
            unsigned key = s_skey[tid];
            int j = (int)(key & 0xFFFFu);
            g_sel_j[tid] = j;
            g_sel_desc[tid] = decode(s_selcol[j]);
        }
    }
}

// ---------------- gather (8 rows/iter, hoisted switch, no NaN branches) -----
#define GPOST(r, VE) { float v = (VE); \
    v = fminf(fmaxf(v, -1e12f), 1e12f); \
    s_out[r][j] = (v - mj) * sji; }
#define GROWS(VE) { _Pragma("unroll") for (int r = 0; r < 8; r++) GPOST(r, VE) }
#define CLIP6(x) fminf(fmaxf((x), -1e6f), 1e6f)

__global__ void __launch_bounds__(512, 3)
gather_kernel(const float* __restrict__ z_flat,
              const float* __restrict__ z_mean,
              const float* __restrict__ z_std,
              const float* __restrict__ x_poly_mean,
              const float* __restrict__ x_poly_std,
              const int* __restrict__ feature_mask,
              float* __restrict__ out) {
    __shared__ float s_zn[8][128];
    __shared__ float s_zp[8][32];
    __shared__ float s_d[8][120];
    __shared__ float s_out[8][512];
    const int tid = threadIdx.x;
    const int desc = g_sel_desc[tid];
    const int kind = desc >> 24;
    const int a = (desc >> 12) & 0xFFF;
    const int b = desc & 0xFFF;
    const int j = g_sel_j[tid];
    const int m = feature_mask[j];
    const float mj = x_poly_mean[m];
    const float sji = frcp(x_poly_std[m]);

    const int row4 = tid >> 5;          // valid for tid<256: 0..7
    const int c4 = (tid & 31) * 4;
    float4 zm4 = make_float4(0.f, 0.f, 0.f, 0.f), zi4 = zm4;
    if (tid < 256) {
        zm4 = *(const float4*)&z_mean[c4];
        float4 zs4 = *(const float4*)&z_std[c4];
        zi4 = make_float4(frcp(zs4.x), frcp(zs4.y), frcp(zs4.z), frcp(zs4.w));
    }
    const bool zpk = ((c4 & 7) == 0);
    const int node2 = (c4 >> 3) * 2;

    const int bp = tid % 120, br = tid / 120;
    int bi = 0, bj = 0;
    if (tid < 480) triu_pair(bp, 16, bi, bj);

    float4 zv = make_float4(0.f, 0.f, 0.f, 0.f);
    if (tid < 256 && blockIdx.x < NG8)
        zv = *(const float4*)&z_flat[(size_t)(blockIdx.x * 8 + row4) * 128 + c4];
    for (int g = blockIdx.x; g < NG8; g += GRID_G) {
        if (tid < 256) {
            float zx = fminf(fmaxf(zv.x, -1e6f), 1e6f);
            float zy = fminf(fmaxf(zv.y, -1e6f), 1e6f);
            float zz = fminf(fmaxf(zv.z, -1e6f), 1e6f);
            float zw = fminf(fmaxf(zv.w, -1e6f), 1e6f);
            float4 w = make_float4((zx - zm4.x) * zi4.x, (zy - zm4.y) * zi4.y,
                                   (zz - zm4.z) * zi4.z, (zw - zm4.w) * zi4.w);
            *(float4*)&s_zn[row4][c4] = w;
            if (zpk) { s_zp[row4][node2] = zx; s_zp[row4][node2 + 1] = zy; }
        }
        __syncthreads();
        int gn = g + GRID_G;
        float4 zv_n = make_float4(0.f, 0.f, 0.f, 0.f);
        if (tid < 256 && gn < NG8)
            zv_n = *(const float4*)&z_flat[(size_t)(gn * 8 + row4) * 128 + c4];
        if (tid < 480) {
            s_d[br][bp]     = pbc_dist(s_zp[br], bi, bj);
            s_d[br + 4][bp] = pbc_dist(s_zp[br + 4], bi, bj);
        }
        __syncthreads();
        switch (kind) {
            case 0: GROWS(s_zn[r][a]); break;
            case 1: GROWS(s_zn[r][a] * s_zn[r][a]); break;
            case 2: GROWS(__sinf(s_zn[r][a])); break;
            case 3: GROWS(__cosf(s_zn[r][a])); break;
            case 4: GROWS(__logf(fabsf(s_zn[r][a]) + 1e-3f)); break;
            case 5: GROWS(__expf(fminf(fmaxf(s_zn[r][a], -10.0f), 2.0f))); break;
            case 6:
                #pragma unroll
                for (int r = 0; r < 8; r++) {
                    float s = 0.0f;
                    #pragma unroll
                    for (int k = 4; k < 8; k++) { float t = s_zn[r][a + k]; s += t * t; }
                    GPOST(r, s);
                }
                break;
            case 7: GROWS(s_zn[r][a] * s_zn[r][b]); break;
            case 16: GROWS(CLIP6(s_d[r][a])); break;
            case 17: GROWS(CLIP6(frcp(s_d[r][a] + 1e-3f))); break;
            case 18: GROWS(CLIP6(frcp(s_d[r][a] * s_d[r][a] + 1e-3f))); break;
            case 19:
                #pragma unroll
                for (int r = 0; r < 8; r++) {
                    float dd = s_d[r][a]; float d2 = dd * dd;
                    GPOST(r, CLIP6(frcp(d2 * dd + 1e-3f)));
                }
                break;
            case 20:
                #pragma unroll
                for (int r = 0; r < 8; r++) {
                    float dd = s_d[r][a]; float d2 = dd * dd;
                    GPOST(r, CLIP6(frcp(d2 * d2 + 1e-3f)));
                }
                break;
            case 21:
                #pragma unroll
                for (int r = 0; r < 8; r++) {
                    float dd = s_d[r][a]; float d2 = dd * dd;
                    GPOST(r, CLIP6(frcp(d2 * d2 * dd + 1e-3f)));
                }
                break;
            case 22:
                #pragma unroll
                for (int r = 0; r < 8; r++) {
                    float dd = s_d[r][a]; float d2 = dd * dd; float d4 = d2 * d2;
                    GPOST(r, CLIP6(frcp(d4 * d2 + 1e-3f)));
                }
                break;
            case 23:
                #pragma unroll
                for (int r = 0; r < 8; r++) {
                    float dd = s_d[r][a]; float d2 = dd * dd; float d4 = d2 * d2;
                    GPOST(r, CLIP6(frcp(d4 * d4 + 1e-3f)));
                }
                break;
            case 24:
                #pragma unroll
                for (int r = 0; r < 8; r++) {
                    float dd = s_d[r][a]; float d2 = dd * dd; float d4 = d2 * d2;
                    GPOST(r, CLIP6(frcp(d4 * d4 * d2 + 1e-3f)));
                }
                break;
            case 25:
                #pragma unroll
                for (int r = 0; r < 8; r++) {
                    float dd = s_d[r][a]; float d2 = dd * dd; float d4 = d2 * d2;
                    GPOST(r, CLIP6(frcp(d4 * d4 * d4 + 1e-3f)));
                }
                break;
            case 26:
                #pragma unroll
                for (int r = 0; r < 8; r++) {
                    float dd = s_d[r][a]; float d2 = dd * dd; float d4 = d2 * d2;
                    float d8 = d4 * d4;
                    GPOST(r, CLIP6(frcp(d8 * d4 * d2 + 1e-3f)));
                }
                break;
            case 27: GROWS(CLIP6(__expf(-s_d[r][a]))); break;
            case 28:
                #pragma unroll
                for (int r = 0; r < 8; r++) {
                    float dd = s_d[r][a];
                    GPOST(r, CLIP6(__expf(-dd) * frcp(dd + 1e-3f)));
                }
                break;
            default: GROWS(CLIP6(__logf(s_d[r][a] + 1e-3f))); break;
        }
        __syncthreads();
        #pragma unroll
        for (int w = 0; w < 2; w++) {
            int f = tid + w * 512;            // float4 index within 8x512 tile
            int r = f >> 7, cc = f & 127;
            float4 wv = *(const float4*)&s_out[r][cc * 4];
            *(float4*)&out[(size_t)(g * 8 + r) * 512 + cc * 4] = wv;
        }
        zv = zv_n;
    }
}

extern "C" void kernel_launch(void* const* d_in, const int* in_sizes, int n_in,
                              void* d_out, int out_size) {
    const float* z_flat      = (const float*)d_in[0];
    const float* z_mean      = (const float*)d_in[1];
    const float* z_std       = (const float*)d_in[2];
    const float* x_poly_mean = (const float*)d_in[3];
    const float* x_poly_std  = (const float*)d_in[4];
    const int*   feature_mask = (const int*)d_in[5];
    float* out = (float*)d_out;

    p1dist_kernel<<<GRID_P, 512>>>(z_flat);
    p1rest_kernel<<<GRID_R, 512>>>(z_flat, z_mean, z_std);
    select_kernel<<<SEL_NB, 1024>>>(feature_mask);
    gather_kernel<<<GRID_G, 512>>>(z_flat, z_mean, z_std,
                                   x_poly_mean, x_poly_std, feature_mask, out);
}

// round 15
// speedup vs baseline: 1.1860x; 1.1860x over previous
#include <cuda_runtime.h>
#include <math.h>

#define NCOLS 3872
#define NROWS 32768
#define NG8   (NROWS / 8)
#define NG16  (NROWS / 16)
#define GRID_P 296
#define GRID_G 444
#define NDV 3360            // 120 pairs * 28 (14 sum + 14 sumsq)
#define NRV 2192            // non-dist columns
#define NVAL (NDV + 2 * NRV)   // 7744
#define CHUNK 37               // 296 / 8
#define SEL_NB 64              // blocks in fused select kernel

__device__ float  g_scr_d[GRID_P * NDV];
__device__ float  g_scr_r[GRID_P * NRV * 2];
__device__ double g_psum[8 * 4096];
__device__ double g_psumsq[8 * 4096];
__device__ unsigned long long g_key[4096];
__device__ int    g_rank[4096];
__device__ int    g_sel_desc[512];
__device__ int    g_sel_j[512];
__device__ unsigned g_bar;

__device__ __forceinline__ float frcp(float x) {
    float r; asm("rcp.approx.f32 %0, %1;" : "=f"(r) : "f"(x)); return r;
}
__device__ __forceinline__ float fsqrt_a(float x) {
    float r; asm("sqrt.approx.f32 %0, %1;" : "=f"(r) : "f"(x)); return r;
}

// multi-use grid barrier: monotonic ticket counter, works across graph replays
__device__ __forceinline__ void grid_barrier() {
    __syncthreads();
    if (threadIdx.x == 0) {
        __threadfence();
        unsigned v = atomicAdd(&g_bar, 1u) + 1u;
        unsigned target = ((v - 1u) / SEL_NB + 1u) * SEL_NB;
        unsigned cur;
        do {
            asm volatile("ld.acquire.gpu.u32 %0, [%1];" : "=r"(cur) : "l"(&g_bar));
        } while (cur < target);
    }
    __syncthreads();
}

__device__ __forceinline__ void triu_pair(int p, int n, int &i, int &j) {
    int ii = 0, rem = p, cnt = n - 1;
    while (rem >= cnt) { rem -= cnt; cnt--; ii++; }
    i = ii; j = ii + 1 + rem;
}

// Column descriptor: kind<<24 | a<<12 | b
__device__ __forceinline__ int decode(int c) {
    int kind, a, b = 0;
    if (c < 128)       { kind = 0; a = c; }
    else if (c < 1808) { int q = c - 128; kind = 16 + q / 120; a = q % 120; }
    else if (c < 1936) { kind = 1; a = c - 1808; }
    else if (c < 2064) { kind = 2; a = c - 1936; }
    else if (c < 2192) { kind = 3; a = c - 2064; }
    else if (c < 2320) { kind = 4; a = c - 2192; }
    else if (c < 2448) { kind = 5; a = c - 2320; }
    else if (c < 2464) { kind = 6; a = (c - 2448) * 8; }
    else if (c < 2912) {
        int idx = c - 2464; int n = idx / 28, pr = idx % 28;
        int i, j; triu_pair(pr, 8, i, j);
        kind = 7; a = n * 8 + i; b = n * 8 + j;
    } else {
        int idx = c - 2912; int pr = idx / 8, k = idx % 8;
        int i, j; triu_pair(pr, 16, i, j);
        kind = 7; a = i * 8 + k; b = j * 8 + k;
    }
    return (kind << 24) | (a << 12) | b;
}

// distance power chain: accumulate 14 values + squares for distance d
__device__ __forceinline__ void dchain(float d, float acc[28]) {
    float dpe = d + 1e-3f;
    float r1 = frcp(dpe);
    float d2 = d * d, d3 = d2 * d, d4 = d2 * d2, d6 = d3 * d3, d8 = d4 * d4;
    float v[14];
    v[0] = d;
    v[1] = r1;
    v[2] = frcp(d2 + 1e-3f);
    v[3] = frcp(d3 + 1e-3f);
    v[4] = frcp(d4 + 1e-3f);
    v[5] = frcp(d4 * d + 1e-3f);
    v[6] = frcp(d6 + 1e-3f);
    v[7] = frcp(d8 + 1e-3f);
    v[8] = frcp(d8 * d2 + 1e-3f);
    v[9] = frcp(d6 * d6 + 1e-3f);
    v[10] = frcp(d8 * d6 + 1e-3f);
    float e = __expf(-d);
    v[11] = e;
    v[12] = e * r1;
    v[13] = __logf(dpe);
    #pragma unroll
    for (int k = 0; k < 14; k++) {
        acc[k] += v[k];
        acc[14 + k] = fmaf(v[k], v[k], acc[14 + k]);
    }
}

__device__ __forceinline__ float pbc_dist(const float* zp, int bi, int bj) {
    float dx = zp[2 * bi]     - zp[2 * bj];
    float dy = zp[2 * bi + 1] - zp[2 * bj + 1];
    dx -= 10.0f * rintf(dx * 0.1f);
    dy -= 10.0f * rintf(dy * 0.1f);
    return fsqrt_a(dx * dx + dy * dy) + 1e-6f;
}

// accumulate 16 rows for one non-dist column; switch hoisted out of row loop
__device__ __forceinline__ void acc16(int desc, const float (*zn)[128],
                                      float &fs, float &fq) {
    const int kind = desc >> 24;
    const int a = (desc >> 12) & 0xFFF;
    const int b = desc & 0xFFF;
    switch (kind) {
        case 0:
            #pragma unroll
            for (int r = 0; r < 16; r++) { float v = zn[r][a]; fs += v; fq = fmaf(v, v, fq); }
            break;
        case 1:
            #pragma unroll
            for (int r = 0; r < 16; r++) { float t = zn[r][a]; float v = t * t; fs += v; fq = fmaf(v, v, fq); }
            break;
        case 2:
            #pragma unroll
            for (int r = 0; r < 16; r++) { float v = __sinf(zn[r][a]); fs += v; fq = fmaf(v, v, fq); }
            break;
        case 3:
            #pragma unroll
            for (int r = 0; r < 16; r++) { float v = __cosf(zn[r][a]); fs += v; fq = fmaf(v, v, fq); }
            break;
        case 4:
            #pragma unroll
            for (int r = 0; r < 16; r++) { float v = __logf(fabsf(zn[r][a]) + 1e-3f); fs += v; fq = fmaf(v, v, fq); }
            break;
        case 5:
            #pragma unroll
            for (int r = 0; r < 16; r++) { float v = __expf(fminf(fmaxf(zn[r][a], -10.0f), 2.0f)); fs += v; fq = fmaf(v, v, fq); }
            break;
        case 6:
            #pragma unroll
            for (int r = 0; r < 16; r++) {
                float s = 0.0f;
                #pragma unroll
                for (int k = 4; k < 8; k++) { float t = zn[r][a + k]; s += t * t; }
                fs += s; fq = fmaf(s, s, fq);
            }
            break;
        default:
            #pragma unroll
            for (int r = 0; r < 16; r++) { float v = zn[r][a] * zn[r][b]; fs += v; fq = fmaf(v, v, fq); }
            break;
    }
}

// ---------------- pass 1a: distance columns (16 rows/iter, float2 coords) --
__global__ void __launch_bounds__(512, 2)
p1dist_kernel(const float* __restrict__ z_flat) {
    __shared__ float s_zp[16][32];
    __shared__ float s_red[NDV];
    const int tid = threadIdx.x;
    const int bid = blockIdx.x;
    const int lrow = tid >> 4;       // valid for tid<256: 0..15
    const int lnode = tid & 15;
    const int bp = tid % 120, br = tid / 120;
    int bi = 0, bj = 0;
    if (tid < 480) triu_pair(bp, 16, bi, bj);

    float acc[28];
    #pragma unroll
    for (int k = 0; k < 28; k++) acc[k] = 0.f;

    float2 zc = make_float2(0.f, 0.f);
    if (tid < 256)
        zc = *(const float2*)&z_flat[(size_t)(bid * 16 + lrow) * 128 + lnode * 8];
    for (int g = bid; g < NG16; g += GRID_P) {
        if (tid < 256) {
            s_zp[lrow][lnode * 2]     = fminf(fmaxf(zc.x, -1e6f), 1e6f);
            s_zp[lrow][lnode * 2 + 1] = fminf(fmaxf(zc.y, -1e6f), 1e6f);
        }
        __syncthreads();
        int gn = g + GRID_P;
        float2 zc_n = make_float2(0.f, 0.f);
        if (tid < 256 && gn < NG16)
            zc_n = *(const float2*)&z_flat[(size_t)(gn * 16 + lrow) * 128 + lnode * 8];
        if (tid < 480) {
            #pragma unroll
            for (int q = 0; q < 4; q++)
                dchain(pbc_dist(s_zp[br + 4 * q], bi, bj), acc);
        }
        __syncthreads();
        zc = zc_n;
    }
    if (tid < 480 && br == 0) {
        #pragma unroll
        for (int k = 0; k < 28; k++) s_red[bp * 28 + k] = acc[k];
    }
    __syncthreads();
    for (int s = 1; s < 4; s++) {
        if (tid < 480 && br == s) {
            #pragma unroll
            for (int k = 0; k < 28; k++) s_red[bp * 28 + k] += acc[k];
        }
        __syncthreads();
    }
    for (int v = tid; v < NDV; v += 512)
        g_scr_d[bid * NDV + v] = s_red[v];
}

// ---------------- pass 1b: non-dist columns (16 rows/iter, float4 staging) -
__global__ void __launch_bounds__(512, 2)
p1rest_kernel(const float* __restrict__ z_flat,
              const float* __restrict__ z_mean,
              const float* __restrict__ z_std) {
    __shared__ float s_zn[16][128];
    const int tid = threadIdx.x;
    const int bid = blockIdx.x;
    const int row4 = tid >> 5;        // 0..15
    const int c4 = (tid & 31) * 4;
    const float4 zm4 = *(const float4*)&z_mean[c4];
    float4 zs4 = *(const float4*)&z_std[c4];
    const float4 zi4 = make_float4(frcp(zs4.x), frcp(zs4.y), frcp(zs4.z), frcp(zs4.w));

    int desc[5]; bool val[5];
    #pragma unroll
    for (int k = 0; k < 5; k++) {
        int i = tid + k * 512;
        val[k] = (i < NRV);
        int col = (i < 128) ? i : i + 1680;
        desc[k] = val[k] ? decode(col) : 0;
    }
    float fs[5], fq[5];
    #pragma unroll
    for (int k = 0; k < 5; k++) { fs[k] = 0.f; fq[k] = 0.f; }

    float4 zv = *(const float4*)&z_flat[(size_t)(bid * 16 + row4) * 128 + c4];
    for (int g = bid; g < NG16; g += GRID_P) {
        {
            float4 w;
            w.x = (fminf(fmaxf(zv.x, -1e6f), 1e6f) - zm4.x) * zi4.x;
            w.y = (fminf(fmaxf(zv.y, -1e6f), 1e6f) - zm4.y) * zi4.y;
            w.z = (fminf(fmaxf(zv.z, -1e6f), 1e6f) - zm4.z) * zi4.z;
            w.w = (fminf(fmaxf(zv.w, -1e6f), 1e6f) - zm4.w) * zi4.w;
            *(float4*)&s_zn[row4][c4] = w;
        }
        __syncthreads();
        int gn = g + GRID_P;
        float4 zv_n = make_float4(0.f, 0.f, 0.f, 0.f);
        if (gn < NG16)
            zv_n = *(const float4*)&z_flat[(size_t)(gn * 16 + row4) * 128 + c4];
        #pragma unroll
        for (int k = 0; k < 5; k++)
            if (val[k]) acc16(desc[k], s_zn, fs[k], fq[k]);
        __syncthreads();
        zv = zv_n;
    }
    #pragma unroll
    for (int k = 0; k < 5; k++) {
        int i = tid + k * 512;
        if (val[k]) {
            g_scr_r[bid * (2 * NRV) + i] = fs[k];
            g_scr_r[bid * (2 * NRV) + NRV + i] = fq[k];
        }
    }
}

// ---------------- fused select: reduce + keys + rank + sel ------------------
__global__ void __launch_bounds__(1024, 1)
select_kernel(const int* __restrict__ feature_mask) {
    __shared__ unsigned long long sk[256];
    __shared__ int s_top[1000];
    __shared__ int s_selcol[512];
    __shared__ unsigned s_skey[512];
    const int tid = threadIdx.x;
    const int tg = blockIdx.x * 1024 + tid;

    // ---- phase 1: chunked f64 reduce (column-ordered output) ----
    {
        int chunk = tg / NVAL;
        int v = tg - chunk * NVAL;
        if (chunk < 8) {
            double s = 0.0;
            int b0 = chunk * CHUNK;
            if (v < NDV) {
                #pragma unroll 4
                for (int b = b0; b < b0 + CHUNK; b++) s += (double)g_scr_d[b * NDV + v];
                int pair = v / 28, k = v % 28;
                int col = 128 + (k % 14) * 120 + pair;
                if (k < 14) g_psum[chunk * 4096 + col] = s;
                else        g_psumsq[chunk * 4096 + col] = s;
            } else {
                int i = v - NDV;
                #pragma unroll 4
                for (int b = b0; b < b0 + CHUNK; b++) s += (double)g_scr_r[b * (2 * NRV) + i];
                int ii = (i < NRV) ? i : i - NRV;
                int col = (ii < 128) ? ii : ii + 1680;
                if (i < NRV) g_psum[chunk * 4096 + col] = s;
                else         g_psumsq[chunk * 4096 + col] = s;
            }
        }
    }
    grid_barrier();

    // ---- phase 2: keys + zero ranks ----
    if (tg < 4096) {
        g_rank[tg] = 0;
        unsigned long long key = 0ull;
        if (tg < NCOLS) {
            double s = 0.0, qq = 0.0;
            #pragma unroll
            for (int ch = 0; ch < 8; ch++) {
                s  += g_psum[ch * 4096 + tg];
                qq += g_psumsq[ch * 4096 + tg];
            }
            double var = (qq - s * (s * (1.0 / 32768.0))) * (1.0 / 32767.0);
            float fv = (float)var;
            unsigned u = __float_as_uint(fv);
            u = (u & 0x80000000u) ? ~u : (u | 0x80000000u);
            key = ((unsigned long long)u << 32) |
                  (unsigned long long)(0xFFFFFFFFu - (unsigned)tg);
        }
        g_key[tg] = key;
    }
    grid_barrier();

    // ---- phase 3: 2-D tiled rank (4 cand-groups x 16 key-slices) ----
    {
        int cg = blockIdx.x & 3;
        int sl = blockIdx.x >> 2;
        if (tid < 256) sk[tid] = g_key[sl * 256 + tid];
        __syncthreads();
        int c = cg * 1024 + tid;
        unsigned long long mykey = g_key[c];
        int r = 0;
        #pragma unroll 8
        for (int i = 0; i < 256; i++) r += (sk[i] > mykey);
        if (r > 0) atomicAdd(&g_rank[c], r);
    }
    grid_barrier();

    // ---- phase 4: scatter + selection + class sort (block 0) ----
    if (blockIdx.x == 0) {
        #pragma unroll
        for (int k = 0; k < 4; k++) {
            int c = tid + k * 1024;
            if (c < NCOLS) {
                int r = g_rank[c];
                if (r < 1000) s_top[r] = c;
            }
        }
        __syncthreads();
        if (tid < 512) {
            int colid = s_top[feature_mask[tid]];
            s_selcol[tid] = colid;
            unsigned cls = (unsigned)(decode(colid) >> 24);
            s_skey[tid] = (cls << 16) | (unsigned)tid;
        }
        __syncthreads();
        for (int k = 2; k <= 512; k <<= 1) {
            for (int j = k >> 1; j > 0; j >>= 1) {
                if (tid < 512) {
                    int ixj = tid ^ j;
                    if (ixj > tid) {
                        unsigned a = s_skey[tid], b = s_skey[ixj];
                        bool up = ((tid & k) == 0);
                        if (up ? (a > b) : (a < b)) { s_skey[tid] = b; s_skey[ixj] = a; }
                    }
                }
                __syncthreads();
            }
        }
        if (tid < 512) {
            unsigned key = s_skey[tid];
            int j = (int)(key & 0xFFFFu);
            g_sel_j[tid] = j;
            g_sel_desc[tid] = decode(s_selcol[j]);
        }
    }
}

// ---------------- gather (8 rows/iter, hoisted switch, no NaN branches) -----
#define GPOST(r, VE) { float v = (VE); \
    v = fminf(fmaxf(v, -1e12f), 1e12f); \
    s_out[r][j] = (v - mj) * sji; }
#define GROWS(VE) { _Pragma("unroll") for (int r = 0; r < 8; r++) GPOST(r, VE) }
#define CLIP6(x) fminf(fmaxf((x), -1e6f), 1e6f)

__global__ void __launch_bounds__(512, 3)
gather_kernel(const float* __restrict__ z_flat,
              const float* __restrict__ z_mean,
              const float* __restrict__ z_std,
              const float* __restrict__ x_poly_mean,
              const float* __restrict__ x_poly_std,
              const int* __restrict__ feature_mask,
              float* __restrict__ out) {
    __shared__ float s_zn[8][128];
    __shared__ float s_zp[8][32];
    __shared__ float s_d[8][120];
    __shared__ float s_out[8][512];
    const int tid = threadIdx.x;
    const int desc = g_sel_desc[tid];
    const int kind = desc >> 24;
    const int a = (desc >> 12) & 0xFFF;
    const int b = desc & 0xFFF;
    const int j = g_sel_j[tid];
    const int m = feature_mask[j];
    const float mj = x_poly_mean[m];
    const float sji = frcp(x_poly_std[m]);

    const int row4 = tid >> 5;          // valid for tid<256: 0..7
    const int c4 = (tid & 31) * 4;
    float4 zm4 = make_float4(0.f, 0.f, 0.f, 0.f), zi4 = zm4;
    if (tid < 256) {
        zm4 = *(const float4*)&z_mean[c4];
        float4 zs4 = *(const float4*)&z_std[c4];
        zi4 = make_float4(frcp(zs4.x), frcp(zs4.y), frcp(zs4.z), frcp(zs4.w));
    }
    const bool zpk = ((c4 & 7) == 0);
    const int node2 = (c4 >> 3) * 2;

    const int bp = tid % 120, br = tid / 120;
    int bi = 0, bj = 0;
    if (tid < 480) triu_pair(bp, 16, bi, bj);

    float4 zv = make_float4(0.f, 0.f, 0.f, 0.f);
    if (tid < 256 && blockIdx.x < NG8)
        zv = *(const float4*)&z_flat[(size_t)(blockIdx.x * 8 + row4) * 128 + c4];
    for (int g = blockIdx.x; g < NG8; g += GRID_G) {
        if (tid < 256) {
            float zx = fminf(fmaxf(zv.x, -1e6f), 1e6f);
            float zy = fminf(fmaxf(zv.y, -1e6f), 1e6f);
            float zz = fminf(fmaxf(zv.z, -1e6f), 1e6f);
            float zw = fminf(fmaxf(zv.w, -1e6f), 1e6f);
            float4 w = make_float4((zx - zm4.x) * zi4.x, (zy - zm4.y) * zi4.y,
                                   (zz - zm4.z) * zi4.z, (zw - zm4.w) * zi4.w);
            *(float4*)&s_zn[row4][c4] = w;
            if (zpk) { s_zp[row4][node2] = zx; s_zp[row4][node2 + 1] = zy; }
        }
        __syncthreads();
        int gn = g + GRID_G;
        float4 zv_n = make_float4(0.f, 0.f, 0.f, 0.f);
        if (tid < 256 && gn < NG8)
            zv_n = *(const float4*)&z_flat[(size_t)(gn * 8 + row4) * 128 + c4];
        if (tid < 480) {
            s_d[br][bp]     = pbc_dist(s_zp[br], bi, bj);
            s_d[br + 4][bp] = pbc_dist(s_zp[br + 4], bi, bj);
        }
        __syncthreads();
        switch (kind) {
            case 0: GROWS(s_zn[r][a]); break;
            case 1: GROWS(s_zn[r][a] * s_zn[r][a]); break;
            case 2: GROWS(__sinf(s_zn[r][a])); break;
            case 3: GROWS(__cosf(s_zn[r][a])); break;
            case 4: GROWS(__logf(fabsf(s_zn[r][a]) + 1e-3f)); break;
            case 5: GROWS(__expf(fminf(fmaxf(s_zn[r][a], -10.0f), 2.0f))); break;
            case 6:
                #pragma unroll
                for (int r = 0; r < 8; r++) {
                    float s = 0.0f;
                    #pragma unroll
                    for (int k = 4; k < 8; k++) { float t = s_zn[r][a + k]; s += t * t; }
                    GPOST(r, s);
                }
                break;
            case 7: GROWS(s_zn[r][a] * s_zn[r][b]); break;
            case 16: GROWS(CLIP6(s_d[r][a])); break;
            case 17: GROWS(CLIP6(frcp(s_d[r][a] + 1e-3f))); break;
            case 18: GROWS(CLIP6(frcp(s_d[r][a] * s_d[r][a] + 1e-3f))); break;
            case 19:
                #pragma unroll
                for (int r = 0; r < 8; r++) {
                    float dd = s_d[r][a]; float d2 = dd * dd;
                    GPOST(r, CLIP6(frcp(d2 * dd + 1e-3f)));
                }
                break;
            case 20:
                #pragma unroll
                for (int r = 0; r < 8; r++) {
                    float dd = s_d[r][a]; float d2 = dd * dd;
                    GPOST(r, CLIP6(frcp(d2 * d2 + 1e-3f)));
                }
                break;
            case 21:
                #pragma unroll
                for (int r = 0; r < 8; r++) {
                    float dd = s_d[r][a]; float d2 = dd * dd;
                    GPOST(r, CLIP6(frcp(d2 * d2 * dd + 1e-3f)));
                }
                break;
            case 22:
                #pragma unroll
                for (int r = 0; r < 8; r++) {
                    float dd = s_d[r][a]; float d2 = dd * dd; float d4 = d2 * d2;
                    GPOST(r, CLIP6(frcp(d4 * d2 + 1e-3f)));
                }
                break;
            case 23:
                #pragma unroll
                for (int r = 0; r < 8; r++) {
                    float dd = s_d[r][a]; float d2 = dd * dd; float d4 = d2 * d2;
                    GPOST(r, CLIP6(frcp(d4 * d4 + 1e-3f)));
                }
                break;
            case 24:
                #pragma unroll
                for (int r = 0; r < 8; r++) {
                    float dd = s_d[r][a]; float d2 = dd * dd; float d4 = d2 * d2;
                    GPOST(r, CLIP6(frcp(d4 * d4 * d2 + 1e-3f)));
                }
                break;
            case 25:
                #pragma unroll
                for (int r = 0; r < 8; r++) {
                    float dd = s_d[r][a]; float d2 = dd * dd; float d4 = d2 * d2;
                    GPOST(r, CLIP6(frcp(d4 * d4 * d4 + 1e-3f)));
                }
                break;
            case 26:
                #pragma unroll
                for (int r = 0; r < 8; r++) {
                    float dd = s_d[r][a]; float d2 = dd * dd; float d4 = d2 * d2;
                    float d8 = d4 * d4;
                    GPOST(r, CLIP6(frcp(d8 * d4 * d2 + 1e-3f)));
                }
                break;
            case 27: GROWS(CLIP6(__expf(-s_d[r][a]))); break;
            case 28:
                #pragma unroll
                for (int r = 0; r < 8; r++) {
                    float dd = s_d[r][a];
                    GPOST(r, CLIP6(__expf(-dd) * frcp(dd + 1e-3f)));
                }
                break;
            default: GROWS(CLIP6(__logf(s_d[r][a] + 1e-3f))); break;
        }
        __syncthreads();
        #pragma unroll
        for (int w = 0; w < 2; w++) {
            int f = tid + w * 512;            // float4 index within 8x512 tile
            int r = f >> 7, cc = f & 127;
            float4 wv = *(const float4*)&s_out[r][cc * 4];
            *(float4*)&out[(size_t)(g * 8 + r) * 512 + cc * 4] = wv;
        }
        zv = zv_n;
    }
}

extern "C" void kernel_launch(void* const* d_in, const int* in_sizes, int n_in,
                              void* d_out, int out_size) {
    const float* z_flat      = (const float*)d_in[0];
    const float* z_mean      = (const float*)d_in[1];
    const float* z_std       = (const float*)d_in[2];
    const float* x_poly_mean = (const float*)d_in[3];
    const float* x_poly_std  = (const float*)d_in[4];
    const int*   feature_mask = (const int*)d_in[5];
    float* out = (float*)d_out;

    p1dist_kernel<<<GRID_P, 512>>>(z_flat);
    p1rest_kernel<<<GRID_P, 512>>>(z_flat, z_mean, z_std);
    select_kernel<<<SEL_NB, 1024>>>(feature_mask);
    gather_kernel<<<GRID_G, 512>>>(z_flat, z_mean, z_std,
                                   x_poly_mean, x_poly_std, feature_mask, out);
}

// round 16
// speedup vs baseline: 1.1989x; 1.0109x over previous
#include <cuda_runtime.h>
#include <math.h>

#define NCOLS 3872
#define NROWS 32768
#define NG8   (NROWS / 8)
#define NG16  (NROWS / 16)
#define GRID_P 296
#define GRID_G 444
#define NDV 3360            // 120 pairs * 28 (14 sum + 14 sumsq)
#define NRV 2192            // non-dist columns
#define NVAL (NDV + 2 * NRV)   // 7744
#define CHUNK 37               // 296 / 8
#define SEL_NB 64              // blocks in fused select kernel

__device__ float  g_scr_d[GRID_P * NDV];
__device__ float  g_scr_r[GRID_P * NRV * 2];
__device__ double g_psum[8 * 4096];
__device__ double g_psumsq[8 * 4096];
__device__ unsigned long long g_key[4096];
__device__ int    g_rank[4096];
__device__ int    g_sel_desc[512];
__device__ int    g_sel_j[512];
__device__ unsigned g_bar;

__device__ __forceinline__ float frcp(float x) {
    float r; asm("rcp.approx.f32 %0, %1;" : "=f"(r) : "f"(x)); return r;
}
__device__ __forceinline__ float fsqrt_a(float x) {
    float r; asm("sqrt.approx.f32 %0, %1;" : "=f"(r) : "f"(x)); return r;
}

// multi-use grid barrier: monotonic ticket counter, works across graph replays
__device__ __forceinline__ void grid_barrier() {
    __syncthreads();
    if (threadIdx.x == 0) {
        __threadfence();
        unsigned v = atomicAdd(&g_bar, 1u) + 1u;
        unsigned target = ((v - 1u) / SEL_NB + 1u) * SEL_NB;
        unsigned cur;
        do {
            asm volatile("ld.acquire.gpu.u32 %0, [%1];" : "=r"(cur) : "l"(&g_bar));
        } while (cur < target);
    }
    __syncthreads();
}

__device__ __forceinline__ void triu_pair(int p, int n, int &i, int &j) {
    int ii = 0, rem = p, cnt = n - 1;
    while (rem >= cnt) { rem -= cnt; cnt--; ii++; }
    i = ii; j = ii + 1 + rem;
}

// Column descriptor: kind<<24 | a<<12 | b
__device__ __forceinline__ int decode(int c) {
    int kind, a, b = 0;
    if (c < 128)       { kind = 0; a = c; }
    else if (c < 1808) { int q = c - 128; kind = 16 + q / 120; a = q % 120; }
    else if (c < 1936) { kind = 1; a = c - 1808; }
    else if (c < 2064) { kind = 2; a = c - 1936; }
    else if (c < 2192) { kind = 3; a = c - 2064; }
    else if (c < 2320) { kind = 4; a = c - 2192; }
    else if (c < 2448) { kind = 5; a = c - 2320; }
    else if (c < 2464) { kind = 6; a = (c - 2448) * 8; }
    else if (c < 2912) {
        int idx = c - 2464; int n = idx / 28, pr = idx % 28;
        int i, j; triu_pair(pr, 8, i, j);
        kind = 7; a = n * 8 + i; b = n * 8 + j;
    } else {
        int idx = c - 2912; int pr = idx / 8, k = idx % 8;
        int i, j; triu_pair(pr, 16, i, j);
        kind = 7; a = i * 8 + k; b = j * 8 + k;
    }
    return (kind << 24) | (a << 12) | b;
}

// distance power chain: accumulate 14 values + squares for distance d
__device__ __forceinline__ void dchain(float d, float acc[28]) {
    float dpe = d + 1e-3f;
    float r1 = frcp(dpe);
    float d2 = d * d, d3 = d2 * d, d4 = d2 * d2, d6 = d3 * d3, d8 = d4 * d4;
    float v[14];
    v[0] = d;
    v[1] = r1;
    v[2] = frcp(d2 + 1e-3f);
    v[3] = frcp(d3 + 1e-3f);
    v[4] = frcp(d4 + 1e-3f);
    v[5] = frcp(d4 * d + 1e-3f);
    v[6] = frcp(d6 + 1e-3f);
    v[7] = frcp(d8 + 1e-3f);
    v[8] = frcp(d8 * d2 + 1e-3f);
    v[9] = frcp(d6 * d6 + 1e-3f);
    v[10] = frcp(d8 * d6 + 1e-3f);
    float e = __expf(-d);
    v[11] = e;
    v[12] = e * r1;
    v[13] = __logf(dpe);
    #pragma unroll
    for (int k = 0; k < 14; k++) {
        acc[k] += v[k];
        acc[14 + k] = fmaf(v[k], v[k], acc[14 + k]);
    }
}

__device__ __forceinline__ float pbc_dist(const float* zp, int bi, int bj) {
    float dx = zp[2 * bi]     - zp[2 * bj];
    float dy = zp[2 * bi + 1] - zp[2 * bj + 1];
    dx -= 10.0f * rintf(dx * 0.1f);
    dy -= 10.0f * rintf(dy * 0.1f);
    return fsqrt_a(dx * dx + dy * dy) + 1e-6f;
}

// accumulate 16 rows for one non-dist column; switch hoisted out of row loop
__device__ __forceinline__ void acc16(int desc, const float (*zn)[128],
                                      float &fs, float &fq) {
    const int kind = desc >> 24;
    const int a = (desc >> 12) & 0xFFF;
    const int b = desc & 0xFFF;
    switch (kind) {
        case 0:
            #pragma unroll
            for (int r = 0; r < 16; r++) { float v = zn[r][a]; fs += v; fq = fmaf(v, v, fq); }
            break;
        case 1:
            #pragma unroll
            for (int r = 0; r < 16; r++) { float t = zn[r][a]; float v = t * t; fs += v; fq = fmaf(v, v, fq); }
            break;
        case 2:
            #pragma unroll
            for (int r = 0; r < 16; r++) { float v = __sinf(zn[r][a]); fs += v; fq = fmaf(v, v, fq); }
            break;
        case 3:
            #pragma unroll
            for (int r = 0; r < 16; r++) { float v = __cosf(zn[r][a]); fs += v; fq = fmaf(v, v, fq); }
            break;
        case 4:
            #pragma unroll
            for (int r = 0; r < 16; r++) { float v = __logf(fabsf(zn[r][a]) + 1e-3f); fs += v; fq = fmaf(v, v, fq); }
            break;
        case 5:
            #pragma unroll
            for (int r = 0; r < 16; r++) { float v = __expf(fminf(fmaxf(zn[r][a], -10.0f), 2.0f)); fs += v; fq = fmaf(v, v, fq); }
            break;
        case 6:
            #pragma unroll
            for (int r = 0; r < 16; r++) {
                float s = 0.0f;
                #pragma unroll
                for (int k = 4; k < 8; k++) { float t = zn[r][a + k]; s += t * t; }
                fs += s; fq = fmaf(s, s, fq);
            }
            break;
        default:
            #pragma unroll
            for (int r = 0; r < 16; r++) { float v = zn[r][a] * zn[r][b]; fs += v; fq = fmaf(v, v, fq); }
            break;
    }
}

// ---------------- pass 1a: distance columns (16 rows/iter, float2 coords) --
__global__ void __launch_bounds__(512, 2)
p1dist_kernel(const float* __restrict__ z_flat) {
    __shared__ float s_zp[16][32];
    __shared__ float s_red[NDV];
    const int tid = threadIdx.x;
    const int bid = blockIdx.x;
    const int lrow = tid >> 4;       // valid for tid<256: 0..15
    const int lnode = tid & 15;
    const int bp = tid % 120, br = tid / 120;
    int bi = 0, bj = 0;
    if (tid < 480) triu_pair(bp, 16, bi, bj);

    float acc[28];
    #pragma unroll
    for (int k = 0; k < 28; k++) acc[k] = 0.f;

    float2 zc = make_float2(0.f, 0.f);
    if (tid < 256)
        zc = *(const float2*)&z_flat[(size_t)(bid * 16 + lrow) * 128 + lnode * 8];
    for (int g = bid; g < NG16; g += GRID_P) {
        if (tid < 256) {
            s_zp[lrow][lnode * 2]     = fminf(fmaxf(zc.x, -1e6f), 1e6f);
            s_zp[lrow][lnode * 2 + 1] = fminf(fmaxf(zc.y, -1e6f), 1e6f);
        }
        __syncthreads();
        int gn = g + GRID_P;
        float2 zc_n = make_float2(0.f, 0.f);
        if (tid < 256 && gn < NG16)
            zc_n = *(const float2*)&z_flat[(size_t)(gn * 16 + lrow) * 128 + lnode * 8];
        if (tid < 480) {
            #pragma unroll
            for (int q = 0; q < 4; q++)
                dchain(pbc_dist(s_zp[br + 4 * q], bi, bj), acc);
        }
        __syncthreads();
        zc = zc_n;
    }
    if (tid < 480 && br == 0) {
        #pragma unroll
        for (int k = 0; k < 28; k++) s_red[bp * 28 + k] = acc[k];
    }
    __syncthreads();
    for (int s = 1; s < 4; s++) {
        if (tid < 480 && br == s) {
            #pragma unroll
            for (int k = 0; k < 28; k++) s_red[bp * 28 + k] += acc[k];
        }
        __syncthreads();
    }
    for (int v = tid; v < NDV; v += 512)
        g_scr_d[bid * NDV + v] = s_red[v];
}

// ---------------- pass 1b: non-dist columns -------------------------------
// warps 0-7 : generic path, 5 col-slots each over the 1232 non-inter columns
// warps 8-15: inter products, register-cached float4 operands, 4 cols/thread
__global__ void __launch_bounds__(512, 2)
p1rest_kernel(const float* __restrict__ z_flat,
              const float* __restrict__ z_mean,
              const float* __restrict__ z_std) {
    __shared__ float s_zn[16][128];
    const int tid = threadIdx.x;
    const int bid = blockIdx.x;
    const int row4 = tid >> 5;        // 0..15
    const int c4 = (tid & 31) * 4;
    const float4 zm4 = *(const float4*)&z_mean[c4];
    float4 zs4 = *(const float4*)&z_std[c4];
    const float4 zi4 = make_float4(frcp(zs4.x), frcp(zs4.y), frcp(zs4.z), frcp(zs4.w));

    const bool is_gen = (tid < 256);
    const int t_int = tid - 256;
    const bool is_int = (t_int >= 0 && t_int < 240);

    int desc[5]; bool val[5];
    #pragma unroll
    for (int k = 0; k < 5; k++) {
        int i = tid + k * 256;
        val[k] = is_gen && (i < 1232);
        int col = (i < 128) ? i : i + 1680;
        desc[k] = val[k] ? decode(col) : 0;
    }
    int aoff = 0, boff = 0;
    if (is_int) {
        int p = t_int >> 1, h = t_int & 1;
        int pi, pj; triu_pair(p, 16, pi, pj);
        aoff = pi * 8 + h * 4;
        boff = pj * 8 + h * 4;
    }

    float fs[5], fq[5];
    #pragma unroll
    for (int k = 0; k < 5; k++) { fs[k] = 0.f; fq[k] = 0.f; }

    float4 zv = *(const float4*)&z_flat[(size_t)(bid * 16 + row4) * 128 + c4];
    for (int g = bid; g < NG16; g += GRID_P) {
        {
            float4 w;
            w.x = (fminf(fmaxf(zv.x, -1e6f), 1e6f) - zm4.x) * zi4.x;
            w.y = (fminf(fmaxf(zv.y, -1e6f), 1e6f) - zm4.y) * zi4.y;
            w.z = (fminf(fmaxf(zv.z, -1e6f), 1e6f) - zm4.z) * zi4.z;
            w.w = (fminf(fmaxf(zv.w, -1e6f), 1e6f) - zm4.w) * zi4.w;
            *(float4*)&s_zn[row4][c4] = w;
        }
        __syncthreads();
        int gn = g + GRID_P;
        float4 zv_n = make_float4(0.f, 0.f, 0.f, 0.f);
        if (gn < NG16)
            zv_n = *(const float4*)&z_flat[(size_t)(gn * 16 + row4) * 128 + c4];
        if (is_gen) {
            #pragma unroll
            for (int k = 0; k < 5; k++)
                if (val[k]) acc16(desc[k], s_zn, fs[k], fq[k]);
        } else if (is_int) {
            #pragma unroll
            for (int r = 0; r < 16; r++) {
                float4 u = *(const float4*)&s_zn[r][aoff];
                float4 w = *(const float4*)&s_zn[r][boff];
                float v0 = u.x * w.x; fs[0] += v0; fq[0] = fmaf(v0, v0, fq[0]);
                float v1 = u.y * w.y; fs[1] += v1; fq[1] = fmaf(v1, v1, fq[1]);
                float v2 = u.z * w.z; fs[2] += v2; fq[2] = fmaf(v2, v2, fq[2]);
                float v3 = u.w * w.w; fs[3] += v3; fq[3] = fmaf(v3, v3, fq[3]);
            }
        }
        __syncthreads();
        zv = zv_n;
    }
    if (is_gen) {
        #pragma unroll
        for (int k = 0; k < 5; k++) {
            int i = tid + k * 256;
            if (val[k]) {
                g_scr_r[bid * (2 * NRV) + i] = fs[k];
                g_scr_r[bid * (2 * NRV) + NRV + i] = fq[k];
            }
        }
    } else if (is_int) {
        int ib = 1232 + (t_int >> 1) * 8 + (t_int & 1) * 4;
        *(float4*)&g_scr_r[bid * (2 * NRV) + ib] =
            make_float4(fs[0], fs[1], fs[2], fs[3]);
        *(float4*)&g_scr_r[bid * (2 * NRV) + NRV + ib] =
            make_float4(fq[0], fq[1], fq[2], fq[3]);
    }
}

// ---------------- fused select: reduce + keys + rank + sel ------------------
__global__ void __launch_bounds__(1024, 1)
select_kernel(const int* __restrict__ feature_mask) {
    __shared__ unsigned long long sk[256];
    __shared__ int s_top[1000];
    __shared__ int s_selcol[512];
    __shared__ unsigned s_skey[512];
    const int tid = threadIdx.x;
    const int tg = blockIdx.x * 1024 + tid;

    // ---- phase 1: chunked f64 reduce (column-ordered output) ----
    {
        int chunk = tg / NVAL;
        int v = tg - chunk * NVAL;
        if (chunk < 8) {
            double s = 0.0;
            int b0 = chunk * CHUNK;
            if (v < NDV) {
                #pragma unroll 4
                for (int b = b0; b < b0 + CHUNK; b++) s += (double)g_scr_d[b * NDV + v];
                int pair = v / 28, k = v % 28;
                int col = 128 + (k % 14) * 120 + pair;
                if (k < 14) g_psum[chunk * 4096 + col] = s;
                else        g_psumsq[chunk * 4096 + col] = s;
            } else {
                int i = v - NDV;
                #pragma unroll 4
                for (int b = b0; b < b0 + CHUNK; b++) s += (double)g_scr_r[b * (2 * NRV) + i];
                int ii = (i < NRV) ? i : i - NRV;
                int col = (ii < 128) ? ii : ii + 1680;
                if (i < NRV) g_psum[chunk * 4096 + col] = s;
                else         g_psumsq[chunk * 4096 + col] = s;
            }
        }
    }
    grid_barrier();

    // ---- phase 2: keys + zero ranks ----
    if (tg < 4096) {
        g_rank[tg] = 0;
        unsigned long long key = 0ull;
        if (tg < NCOLS) {
            double s = 0.0, qq = 0.0;
            #pragma unroll
            for (int ch = 0; ch < 8; ch++) {
                s  += g_psum[ch * 4096 + tg];
                qq += g_psumsq[ch * 4096 + tg];
            }
            double var = (qq - s * (s * (1.0 / 32768.0))) * (1.0 / 32767.0);
            float fv = (float)var;
            unsigned u = __float_as_uint(fv);
            u = (u & 0x80000000u) ? ~u : (u | 0x80000000u);
            key = ((unsigned long long)u << 32) |
                  (unsigned long long)(0xFFFFFFFFu - (unsigned)tg);
        }
        g_key[tg] = key;
    }
    grid_barrier();

    // ---- phase 3: 2-D tiled rank (4 cand-groups x 16 key-slices) ----
    {
        int cg = blockIdx.x & 3;
        int sl = blockIdx.x >> 2;
        if (tid < 256) sk[tid] = g_key[sl * 256 + tid];
        __syncthreads();
        int c = cg * 1024 + tid;
        unsigned long long mykey = g_key[c];
        int r = 0;
        #pragma unroll 8
        for (int i = 0; i < 256; i++) r += (sk[i] > mykey);
        if (r > 0) atomicAdd(&g_rank[c], r);
    }
    grid_barrier();

    // ---- phase 4: scatter + selection + class sort (block 0) ----
    if (blockIdx.x == 0) {
        #pragma unroll
        for (int k = 0; k < 4; k++) {
            int c = tid + k * 1024;
            if (c < NCOLS) {
                int r = g_rank[c];
                if (r < 1000) s_top[r] = c;
            }
        }
        __syncthreads();
        if (tid < 512) {
            int colid = s_top[feature_mask[tid]];
            s_selcol[tid] = colid;
            unsigned cls = (unsigned)(decode(colid) >> 24);
            s_skey[tid] = (cls << 16) | (unsigned)tid;
        }
        __syncthreads();
        for (int k = 2; k <= 512; k <<= 1) {
            for (int j = k >> 1; j > 0; j >>= 1) {
                if (tid < 512) {
                    int ixj = tid ^ j;
                    if (ixj > tid) {
                        unsigned a = s_skey[tid], b = s_skey[ixj];
                        bool up = ((tid & k) == 0);
                        if (up ? (a > b) : (a < b)) { s_skey[tid] = b; s_skey[ixj] = a; }
                    }
                }
                __syncthreads();
            }
        }
        if (tid < 512) {
            unsigned key = s_skey[tid];
            int j = (int)(key & 0xFFFFu);
            g_sel_j[tid] = j;
            g_sel_desc[tid] = decode(s_selcol[j]);
        }
    }
}

// ---------------- gather (8 rows/iter, hoisted switch, no NaN branches) -----
#define GPOST(r, VE) { float v = (VE); \
    v = fminf(fmaxf(v, -1e12f), 1e12f); \
    s_out[r][j] = (v - mj) * sji; }
#define GROWS(VE) { _Pragma("unroll") for (int r = 0; r < 8; r++) GPOST(r, VE) }
#define CLIP6(x) fminf(fmaxf((x), -1e6f), 1e6f)

__global__ void __launch_bounds__(512, 3)
gather_kernel(const float* __restrict__ z_flat,
              const float* __restrict__ z_mean,
              const float* __restrict__ z_std,
              const float* __restrict__ x_poly_mean,
              const float* __restrict__ x_poly_std,
              const int* __restrict__ feature_mask,
              float* __restrict__ out) {
    __shared__ float s_zn[8][128];
    __shared__ float s_zp[8][32];
    __shared__ float s_d[8][120];
    __shared__ float s_out[8][512];
    const int tid = threadIdx.x;
    const int desc = g_sel_desc[tid];
    const int kind = desc >> 24;
    const int a = (desc >> 12) & 0xFFF;
    const int b = desc & 0xFFF;
    const int j = g_sel_j[tid];
    const int m = feature_mask[j];
    const float mj = x_poly_mean[m];
    const float sji = frcp(x_poly_std[m]);

    const int row4 = tid >> 5;          // valid for tid<256: 0..7
    const int c4 = (tid & 31) * 4;
    float4 zm4 = make_float4(0.f, 0.f, 0.f, 0.f), zi4 = zm4;
    if (tid < 256) {
        zm4 = *(const float4*)&z_mean[c4];
        float4 zs4 = *(const float4*)&z_std[c4];
        zi4 = make_float4(frcp(zs4.x), frcp(zs4.y), frcp(zs4.z), frcp(zs4.w));
    }
    const bool zpk = ((c4 & 7) == 0);
    const int node2 = (c4 >> 3) * 2;

    const int bp = tid % 120, br = tid / 120;
    int bi = 0, bj = 0;
    if (tid < 480) triu_pair(bp, 16, bi, bj);

    float4 zv = make_float4(0.f, 0.f, 0.f, 0.f);
    if (tid < 256 && blockIdx.x < NG8)
        zv = *(const float4*)&z_flat[(size_t)(blockIdx.x * 8 + row4) * 128 + c4];
    for (int g = blockIdx.x; g < NG8; g += GRID_G) {
        if (tid < 256) {
            float zx = fminf(fmaxf(zv.x, -1e6f), 1e6f);
            float zy = fminf(fmaxf(zv.y, -1e6f), 1e6f);
            float zz = fminf(fmaxf(zv.z, -1e6f), 1e6f);
            float zw = fminf(fmaxf(zv.w, -1e6f), 1e6f);
            float4 w = make_float4((zx - zm4.x) * zi4.x, (zy - zm4.y) * zi4.y,
                                   (zz - zm4.z) * zi4.z, (zw - zm4.w) * zi4.w);
            *(float4*)&s_zn[row4][c4] = w;
            if (zpk) { s_zp[row4][node2] = zx; s_zp[row4][node2 + 1] = zy; }
        }
        __syncthreads();
        int gn = g + GRID_G;
        float4 zv_n = make_float4(0.f, 0.f, 0.f, 0.f);
        if (tid < 256 && gn < NG8)
            zv_n = *(const float4*)&z_flat[(size_t)(gn * 8 + row4) * 128 + c4];
        if (tid < 480) {
            s_d[br][bp]     = pbc_dist(s_zp[br], bi, bj);
            s_d[br + 4][bp] = pbc_dist(s_zp[br + 4], bi, bj);
        }
        __syncthreads();
        switch (kind) {
            case 0: GROWS(s_zn[r][a]); break;
            case 1: GROWS(s_zn[r][a] * s_zn[r][a]); break;
            case 2: GROWS(__sinf(s_zn[r][a])); break;
            case 3: GROWS(__cosf(s_zn[r][a])); break;
            case 4: GROWS(__logf(fabsf(s_zn[r][a]) + 1e-3f)); break;
            case 5: GROWS(__expf(fminf(fmaxf(s_zn[r][a], -10.0f), 2.0f))); break;
            case 6:
                #pragma unroll
                for (int r = 0; r < 8; r++) {
                    float s = 0.0f;
                    #pragma unroll
                    for (int k = 4; k < 8; k++) { float t = s_zn[r][a + k]; s += t * t; }
                    GPOST(r, s);
                }
                break;
            case 7: GROWS(s_zn[r][a] * s_zn[r][b]); break;
            case 16: GROWS(CLIP6(s_d[r][a])); break;
            case 17: GROWS(CLIP6(frcp(s_d[r][a] + 1e-3f))); break;
            case 18: GROWS(CLIP6(frcp(s_d[r][a] * s_d[r][a] + 1e-3f))); break;
            case 19:
                #pragma unroll
                for (int r = 0; r < 8; r++) {
                    float dd = s_d[r][a]; float d2 = dd * dd;
                    GPOST(r, CLIP6(frcp(d2 * dd + 1e-3f)));
                }
                break;
            case 20:
                #pragma unroll
                for (int r = 0; r < 8; r++) {
                    float dd = s_d[r][a]; float d2 = dd * dd;
                    GPOST(r, CLIP6(frcp(d2 * d2 + 1e-3f)));
                }
                break;
            case 21:
                #pragma unroll
                for (int r = 0; r < 8; r++) {
                    float dd = s_d[r][a]; float d2 = dd * dd;
                    GPOST(r, CLIP6(frcp(d2 * d2 * dd + 1e-3f)));
                }
                break;
            case 22:
                #pragma unroll
                for (int r = 0; r < 8; r++) {
                    float dd = s_d[r][a]; float d2 = dd * dd; float d4 = d2 * d2;
                    GPOST(r, CLIP6(frcp(d4 * d2 + 1e-3f)));
                }
                break;
            case 23:
                #pragma unroll
                for (int r = 0; r < 8; r++) {
                    float dd = s_d[r][a]; float d2 = dd * dd; float d4 = d2 * d2;
                    GPOST(r, CLIP6(frcp(d4 * d4 + 1e-3f)));
                }
                break;
            case 24:
                #pragma unroll
                for (int r = 0; r < 8; r++) {
                    float dd = s_d[r][a]; float d2 = dd * dd; float d4 = d2 * d2;
                    GPOST(r, CLIP6(frcp(d4 * d4 * d2 + 1e-3f)));
                }
                break;
            case 25:
                #pragma unroll
                for (int r = 0; r < 8; r++) {
                    float dd = s_d[r][a]; float d2 = dd * dd; float d4 = d2 * d2;
                    GPOST(r, CLIP6(frcp(d4 * d4 * d4 + 1e-3f)));
                }
                break;
            case 26:
                #pragma unroll
                for (int r = 0; r < 8; r++) {
                    float dd = s_d[r][a]; float d2 = dd * dd; float d4 = d2 * d2;
                    float d8 = d4 * d4;
                    GPOST(r, CLIP6(frcp(d8 * d4 * d2 + 1e-3f)));
                }
                break;
            case 27: GROWS(CLIP6(__expf(-s_d[r][a]))); break;
            case 28:
                #pragma unroll
                for (int r = 0; r < 8; r++) {
                    float dd = s_d[r][a];
                    GPOST(r, CLIP6(__expf(-dd) * frcp(dd + 1e-3f)));
                }
                break;
            default: GROWS(CLIP6(__logf(s_d[r][a] + 1e-3f))); break;
        }
        __syncthreads();
        #pragma unroll
        for (int w = 0; w < 2; w++) {
            int f = tid + w * 512;            // float4 index within 8x512 tile
            int r = f >> 7, cc = f & 127;
            float4 wv = *(const float4*)&s_out[r][cc * 4];
            *(float4*)&out[(size_t)(g * 8 + r) * 512 + cc * 4] = wv;
        }
        zv = zv_n;
    }
}

extern "C" void kernel_launch(void* const* d_in, const int* in_sizes, int n_in,
                              void* d_out, int out_size) {
    const float* z_flat      = (const float*)d_in[0];
    const float* z_mean      = (const float*)d_in[1];
    const float* z_std       = (const float*)d_in[2];
    const float* x_poly_mean = (const float*)d_in[3];
    const float* x_poly_std  = (const float*)d_in[4];
    const int*   feature_mask = (const int*)d_in[5];
    float* out = (float*)d_out;

    p1dist_kernel<<<GRID_P, 512>>>(z_flat);
    p1rest_kernel<<<GRID_P, 512>>>(z_flat, z_mean, z_std);
    select_kernel<<<SEL_NB, 1024>>>(feature_mask);
    gather_kernel<<<GRID_G, 512>>>(z_flat, z_mean, z_std,
                                   x_poly_mean, x_poly_std, feature_mask, out);
}

// round 17
// speedup vs baseline: 1.2238x; 1.0208x over previous
#include <cuda_runtime.h>
#include <math.h>

#define NCOLS 3872
#define NROWS 32768
#define NG8   (NROWS / 8)
#define NG16  (NROWS / 16)
#define GRID_P 296
#define GRID_G 444
#define NDV 3360            // 120 pairs * 28 (14 sum + 14 sumsq)
#define NRV 2192            // non-dist columns
#define NVAL (NDV + 2 * NRV)   // 7744
#define CHUNK 37               // 296 / 8
#define SEL_NB 64              // blocks in fused select kernel

__device__ float  g_scr_d[GRID_P * NDV];
__device__ float  g_scr_r[GRID_P * NRV * 2];
__device__ double g_psum[8 * 4096];
__device__ double g_psumsq[8 * 4096];
__device__ unsigned long long g_key[4096];
__device__ int    g_rank[4096];
__device__ int    g_sel_desc[512];
__device__ int    g_sel_j[512];
__device__ unsigned g_bar;

__device__ __forceinline__ float frcp(float x) {
    float r; asm("rcp.approx.f32 %0, %1;" : "=f"(r) : "f"(x)); return r;
}
__device__ __forceinline__ float fsqrt_a(float x) {
    float r; asm("sqrt.approx.f32 %0, %1;" : "=f"(r) : "f"(x)); return r;
}

// multi-use grid barrier: monotonic ticket counter, works across graph replays
__device__ __forceinline__ void grid_barrier() {
    __syncthreads();
    if (threadIdx.x == 0) {
        __threadfence();
        unsigned v = atomicAdd(&g_bar, 1u) + 1u;
        unsigned target = ((v - 1u) / SEL_NB + 1u) * SEL_NB;
        unsigned cur;
        do {
            asm volatile("ld.acquire.gpu.u32 %0, [%1];" : "=r"(cur) : "l"(&g_bar));
        } while (cur < target);
    }
    __syncthreads();
}

__device__ __forceinline__ void triu_pair(int p, int n, int &i, int &j) {
    int ii = 0, rem = p, cnt = n - 1;
    while (rem >= cnt) { rem -= cnt; cnt--; ii++; }
    i = ii; j = ii + 1 + rem;
}

// Column descriptor: kind<<24 | a<<12 | b
__device__ __forceinline__ int decode(int c) {
    int kind, a, b = 0;
    if (c < 128)       { kind = 0; a = c; }
    else if (c < 1808) { int q = c - 128; kind = 16 + q / 120; a = q % 120; }
    else if (c < 1936) { kind = 1; a = c - 1808; }
    else if (c < 2064) { kind = 2; a = c - 1936; }
    else if (c < 2192) { kind = 3; a = c - 2064; }
    else if (c < 2320) { kind = 4; a = c - 2192; }
    else if (c < 2448) { kind = 5; a = c - 2320; }
    else if (c < 2464) { kind = 6; a = (c - 2448) * 8; }
    else if (c < 2912) {
        int idx = c - 2464; int n = idx / 28, pr = idx % 28;
        int i, j; triu_pair(pr, 8, i, j);
        kind = 7; a = n * 8 + i; b = n * 8 + j;
    } else {
        int idx = c - 2912; int pr = idx / 8, k = idx % 8;
        int i, j; triu_pair(pr, 16, i, j);
        kind = 7; a = i * 8 + k; b = j * 8 + k;
    }
    return (kind << 24) | (a << 12) | b;
}

// distance power chain: accumulate 14 values + squares for distance d
__device__ __forceinline__ void dchain(float d, float acc[28]) {
    float dpe = d + 1e-3f;
    float r1 = frcp(dpe);
    float d2 = d * d, d3 = d2 * d, d4 = d2 * d2, d6 = d3 * d3, d8 = d4 * d4;
    float v[14];
    v[0] = d;
    v[1] = r1;
    v[2] = frcp(d2 + 1e-3f);
    v[3] = frcp(d3 + 1e-3f);
    v[4] = frcp(d4 + 1e-3f);
    v[5] = frcp(d4 * d + 1e-3f);
    v[6] = frcp(d6 + 1e-3f);
    v[7] = frcp(d8 + 1e-3f);
    v[8] = frcp(d8 * d2 + 1e-3f);
    v[9] = frcp(d6 * d6 + 1e-3f);
    v[10] = frcp(d8 * d6 + 1e-3f);
    float e = __expf(-d);
    v[11] = e;
    v[12] = e * r1;
    v[13] = __logf(dpe);
    #pragma unroll
    for (int k = 0; k < 14; k++) {
        acc[k] += v[k];
        acc[14 + k] = fmaf(v[k], v[k], acc[14 + k]);
    }
}

__device__ __forceinline__ float pbc_dist(const float* zp, int bi, int bj) {
    float dx = zp[2 * bi]     - zp[2 * bj];
    float dy = zp[2 * bi + 1] - zp[2 * bj + 1];
    dx -= 10.0f * rintf(dx * 0.1f);
    dy -= 10.0f * rintf(dy * 0.1f);
    return fsqrt_a(dx * dx + dy * dy) + 1e-6f;
}

// accumulate 16 rows for one non-dist column; switch hoisted out of row loop
__device__ __forceinline__ void acc16(int desc, const float (*zn)[128],
                                      float &fs, float &fq) {
    const int kind = desc >> 24;
    const int a = (desc >> 12) & 0xFFF;
    const int b = desc & 0xFFF;
    switch (kind) {
        case 6:
            #pragma unroll
            for (int r = 0; r < 16; r++) {
                float s = 0.0f;
                #pragma unroll
                for (int k = 4; k < 8; k++) { float t = zn[r][a + k]; s += t * t; }
                fs += s; fq = fmaf(s, s, fq);
            }
            break;
        default:
            #pragma unroll
            for (int r = 0; r < 16; r++) { float v = zn[r][a] * zn[r][b]; fs += v; fq = fmaf(v, v, fq); }
            break;
    }
}

// ---------------- pass 1a: distance columns (16 rows/iter, float2 coords) --
__global__ void __launch_bounds__(512, 2)
p1dist_kernel(const float* __restrict__ z_flat) {
    __shared__ float s_zp[16][32];
    __shared__ float s_red[NDV];
    const int tid = threadIdx.x;
    const int bid = blockIdx.x;
    const int lrow = tid >> 4;       // valid for tid<256: 0..15
    const int lnode = tid & 15;
    const int bp = tid % 120, br = tid / 120;
    int bi = 0, bj = 0;
    if (tid < 480) triu_pair(bp, 16, bi, bj);

    float acc[28];
    #pragma unroll
    for (int k = 0; k < 28; k++) acc[k] = 0.f;

    float2 zc = make_float2(0.f, 0.f);
    if (tid < 256)
        zc = *(const float2*)&z_flat[(size_t)(bid * 16 + lrow) * 128 + lnode * 8];
    for (int g = bid; g < NG16; g += GRID_P) {
        if (tid < 256) {
            s_zp[lrow][lnode * 2]     = fminf(fmaxf(zc.x, -1e6f), 1e6f);
            s_zp[lrow][lnode * 2 + 1] = fminf(fmaxf(zc.y, -1e6f), 1e6f);
        }
        __syncthreads();
        int gn = g + GRID_P;
        float2 zc_n = make_float2(0.f, 0.f);
        if (tid < 256 && gn < NG16)
            zc_n = *(const float2*)&z_flat[(size_t)(gn * 16 + lrow) * 128 + lnode * 8];
        if (tid < 480) {
            #pragma unroll
            for (int q = 0; q < 4; q++)
                dchain(pbc_dist(s_zp[br + 4 * q], bi, bj), acc);
        }
        __syncthreads();
        zc = zc_n;
    }
    if (tid < 480 && br == 0) {
        #pragma unroll
        for (int k = 0; k < 28; k++) s_red[bp * 28 + k] = acc[k];
    }
    __syncthreads();
    for (int s = 1; s < 4; s++) {
        if (tid < 480 && br == s) {
            #pragma unroll
            for (int k = 0; k < 28; k++) s_red[bp * 28 + k] += acc[k];
        }
        __syncthreads();
    }
    for (int v = tid; v < NDV; v += 512)
        g_scr_d[bid * NDV + v] = s_red[v];
}

// ---------------- pass 1b: non-dist columns, role-balanced ------------------
// tid   0-127: zn-family (zn, zn^2, sin, cos, log, exp of zn[tid]) 1 LDS/row
// tid 128-367: inter products, float4-cached, 4 cols/thread (240 active)
// tid 368-495: psq + intra via generic path, 4 slots each (464 cols)
__global__ void __launch_bounds__(512, 2)
p1rest_kernel(const float* __restrict__ z_flat,
              const float* __restrict__ z_mean,
              const float* __restrict__ z_std) {
    __shared__ float s_zn[16][128];
    const int tid = threadIdx.x;
    const int bid = blockIdx.x;
    const int row4 = tid >> 5;        // 0..15
    const int c4 = (tid & 31) * 4;
    const float4 zm4 = *(const float4*)&z_mean[c4];
    float4 zs4 = *(const float4*)&z_std[c4];
    const float4 zi4 = make_float4(frcp(zs4.x), frcp(zs4.y), frcp(zs4.z), frcp(zs4.w));

    const bool is_fam = (tid < 128);
    const int t_int = tid - 128;
    const bool is_int = (t_int >= 0 && t_int < 240);
    const int t_gen = tid - 368;
    const bool is_gen = (t_gen >= 0 && t_gen < 128);

    int desc[4]; bool val[4];
    #pragma unroll
    for (int k = 0; k < 4; k++) {
        int i = t_gen + k * 128;              // rest-idx - 768
        val[k] = is_gen && (i < 464);
        desc[k] = val[k] ? decode(2448 + i) : 0;
    }
    int aoff = 0, boff = 0;
    if (is_int) {
        int p = t_int >> 1, h = t_int & 1;
        int pi, pj; triu_pair(p, 16, pi, pj);
        aoff = pi * 8 + h * 4;
        boff = pj * 8 + h * 4;
    }

    float fs[6], fq[6];
    #pragma unroll
    for (int k = 0; k < 6; k++) { fs[k] = 0.f; fq[k] = 0.f; }

    float4 zv = *(const float4*)&z_flat[(size_t)(bid * 16 + row4) * 128 + c4];
    for (int g = bid; g < NG16; g += GRID_P) {
        {
            float4 w;
            w.x = (fminf(fmaxf(zv.x, -1e6f), 1e6f) - zm4.x) * zi4.x;
            w.y = (fminf(fmaxf(zv.y, -1e6f), 1e6f) - zm4.y) * zi4.y;
            w.z = (fminf(fmaxf(zv.z, -1e6f), 1e6f) - zm4.z) * zi4.z;
            w.w = (fminf(fmaxf(zv.w, -1e6f), 1e6f) - zm4.w) * zi4.w;
            *(float4*)&s_zn[row4][c4] = w;
        }
        __syncthreads();
        int gn = g + GRID_P;
        float4 zv_n = make_float4(0.f, 0.f, 0.f, 0.f);
        if (gn < NG16)
            zv_n = *(const float4*)&z_flat[(size_t)(gn * 16 + row4) * 128 + c4];
        if (is_fam) {
            #pragma unroll
            for (int r = 0; r < 16; r++) {
                float z = s_zn[r][tid];
                fs[0] += z;            fq[0] = fmaf(z, z, fq[0]);
                float v1 = z * z;      fs[1] += v1; fq[1] = fmaf(v1, v1, fq[1]);
                float v2 = __sinf(z);  fs[2] += v2; fq[2] = fmaf(v2, v2, fq[2]);
                float v3 = __cosf(z);  fs[3] += v3; fq[3] = fmaf(v3, v3, fq[3]);
                float v4 = __logf(fabsf(z) + 1e-3f);
                                       fs[4] += v4; fq[4] = fmaf(v4, v4, fq[4]);
                float v5 = __expf(fminf(fmaxf(z, -10.0f), 2.0f));
                                       fs[5] += v5; fq[5] = fmaf(v5, v5, fq[5]);
            }
        } else if (is_int) {
            #pragma unroll
            for (int r = 0; r < 16; r++) {
                float4 u = *(const float4*)&s_zn[r][aoff];
                float4 w = *(const float4*)&s_zn[r][boff];
                float v0 = u.x * w.x; fs[0] += v0; fq[0] = fmaf(v0, v0, fq[0]);
                float v1 = u.y * w.y; fs[1] += v1; fq[1] = fmaf(v1, v1, fq[1]);
                float v2 = u.z * w.z; fs[2] += v2; fq[2] = fmaf(v2, v2, fq[2]);
                float v3 = u.w * w.w; fs[3] += v3; fq[3] = fmaf(v3, v3, fq[3]);
            }
        } else if (is_gen) {
            #pragma unroll
            for (int k = 0; k < 4; k++)
                if (val[k]) acc16(desc[k], s_zn, fs[k], fq[k]);
        }
        __syncthreads();
        zv = zv_n;
    }
    float* scr = &g_scr_r[bid * (2 * NRV)];
    if (is_fam) {
        #pragma unroll
        for (int k = 0; k < 6; k++) {
            scr[k * 128 + tid] = fs[k];
            scr[NRV + k * 128 + tid] = fq[k];
        }
    } else if (is_int) {
        int ib = 1232 + (t_int >> 1) * 8 + (t_int & 1) * 4;
        *(float4*)&scr[ib] = make_float4(fs[0], fs[1], fs[2], fs[3]);
        *(float4*)&scr[NRV + ib] = make_float4(fq[0], fq[1], fq[2], fq[3]);
    } else if (is_gen) {
        #pragma unroll
        for (int k = 0; k < 4; k++) {
            int i = 768 + t_gen + k * 128;
            if (val[k]) {
                scr[i] = fs[k];
                scr[NRV + i] = fq[k];
            }
        }
    }
}

// ---------------- fused select: reduce + keys + rank + sel ------------------
__global__ void __launch_bounds__(1024, 1)
select_kernel(const int* __restrict__ feature_mask) {
    __shared__ unsigned long long sk[256];
    __shared__ int s_top[1000];
    __shared__ int s_selcol[512];
    __shared__ unsigned s_skey[512];
    const int tid = threadIdx.x;
    const int tg = blockIdx.x * 1024 + tid;

    // ---- phase 1: chunked f64 reduce (column-ordered output) ----
    {
        int chunk = tg / NVAL;
        int v = tg - chunk * NVAL;
        if (chunk < 8) {
            double s = 0.0;
            int b0 = chunk * CHUNK;
            if (v < NDV) {
                #pragma unroll 4
                for (int b = b0; b < b0 + CHUNK; b++) s += (double)g_scr_d[b * NDV + v];
                int pair = v / 28, k = v % 28;
                int col = 128 + (k % 14) * 120 + pair;
                if (k < 14) g_psum[chunk * 4096 + col] = s;
                else        g_psumsq[chunk * 4096 + col] = s;
            } else {
                int i = v - NDV;
                #pragma unroll 4
                for (int b = b0; b < b0 + CHUNK; b++) s += (double)g_scr_r[b * (2 * NRV) + i];
                int ii = (i < NRV) ? i : i - NRV;
                int col = (ii < 128) ? ii : ii + 1680;
                if (i < NRV) g_psum[chunk * 4096 + col] = s;
                else         g_psumsq[chunk * 4096 + col] = s;
            }
        }
    }
    grid_barrier();

    // ---- phase 2: keys + zero ranks ----
    if (tg < 4096) {
        g_rank[tg] = 0;
        unsigned long long key = 0ull;
        if (tg < NCOLS) {
            double s = 0.0, qq = 0.0;
            #pragma unroll
            for (int ch = 0; ch < 8; ch++) {
                s  += g_psum[ch * 4096 + tg];
                qq += g_psumsq[ch * 4096 + tg];
            }
            double var = (qq - s * (s * (1.0 / 32768.0))) * (1.0 / 32767.0);
            float fv = (float)var;
            unsigned u = __float_as_uint(fv);
            u = (u & 0x80000000u) ? ~u : (u | 0x80000000u);
            key = ((unsigned long long)u << 32) |
                  (unsigned long long)(0xFFFFFFFFu - (unsigned)tg);
        }
        g_key[tg] = key;
    }
    grid_barrier();

    // ---- phase 3: 2-D tiled rank (4 cand-groups x 16 key-slices) ----
    {
        int cg = blockIdx.x & 3;
        int sl = blockIdx.x >> 2;
        if (tid < 256) sk[tid] = g_key[sl * 256 + tid];
        __syncthreads();
        int c = cg * 1024 + tid;
        unsigned long long mykey = g_key[c];
        int r = 0;
        #pragma unroll 8
        for (int i = 0; i < 256; i++) r += (sk[i] > mykey);
        if (r > 0) atomicAdd(&g_rank[c], r);
    }
    grid_barrier();

    // ---- phase 4: scatter + selection + class sort (block 0) ----
    if (blockIdx.x == 0) {
        #pragma unroll
        for (int k = 0; k < 4; k++) {
            int c = tid + k * 1024;
            if (c < NCOLS) {
                int r = g_rank[c];
                if (r < 1000) s_top[r] = c;
            }
        }
        __syncthreads();
        if (tid < 512) {
            int colid = s_top[feature_mask[tid]];
            s_selcol[tid] = colid;
            unsigned cls = (unsigned)(decode(colid) >> 24);
            s_skey[tid] = (cls << 16) | (unsigned)tid;
        }
        __syncthreads();
        for (int k = 2; k <= 512; k <<= 1) {
            for (int j = k >> 1; j > 0; j >>= 1) {
                if (tid < 512) {
                    int ixj = tid ^ j;
                    if (ixj > tid) {
                        unsigned a = s_skey[tid], b = s_skey[ixj];
                        bool up = ((tid & k) == 0);
                        if (up ? (a > b) : (a < b)) { s_skey[tid] = b; s_skey[ixj] = a; }
                    }
                }
                __syncthreads();
            }
        }
        if (tid < 512) {
            unsigned key = s_skey[tid];
            int j = (int)(key & 0xFFFFu);
            g_sel_j[tid] = j;
            g_sel_desc[tid] = decode(s_selcol[j]);
        }
    }
}

// ---------------- gather (8 rows/iter, hoisted switch, no NaN branches) -----
#define GPOST(r, VE) { float v = (VE); \
    v = fminf(fmaxf(v, -1e12f), 1e12f); \
    s_out[r][j] = (v - mj) * sji; }
#define GROWS(VE) { _Pragma("unroll") for (int r = 0; r < 8; r++) GPOST(r, VE) }
#define CLIP6(x) fminf(fmaxf((x), -1e6f), 1e6f)

__global__ void __launch_bounds__(512, 3)
gather_kernel(const float* __restrict__ z_flat,
              const float* __restrict__ z_mean,
              const float* __restrict__ z_std,
              const float* __restrict__ x_poly_mean,
              const float* __restrict__ x_poly_std,
              const int* __restrict__ feature_mask,
              float* __restrict__ out) {
    __shared__ float s_zn[8][128];
    __shared__ float s_zp[8][32];
    __shared__ float s_d[8][120];
    __shared__ float s_out[8][512];
    const int tid = threadIdx.x;
    const int desc = g_sel_desc[tid];
    const int kind = desc >> 24;
    const int a = (desc >> 12) & 0xFFF;
    const int b = desc & 0xFFF;
    const int j = g_sel_j[tid];
    const int m = feature_mask[j];
    const float mj = x_poly_mean[m];
    const float sji = frcp(x_poly_std[m]);

    const int row4 = tid >> 5;          // valid for tid<256: 0..7
    const int c4 = (tid & 31) * 4;
    float4 zm4 = make_float4(0.f, 0.f, 0.f, 0.f), zi4 = zm4;
    if (tid < 256) {
        zm4 = *(const float4*)&z_mean[c4];
        float4 zs4 = *(const float4*)&z_std[c4];
        zi4 = make_float4(frcp(zs4.x), frcp(zs4.y), frcp(zs4.z), frcp(zs4.w));
    }
    const bool zpk = ((c4 & 7) == 0);
    const int node2 = (c4 >> 3) * 2;

    const int bp = tid % 120, br = tid / 120;
    int bi = 0, bj = 0;
    if (tid < 480) triu_pair(bp, 16, bi, bj);

    float4 zv = make_float4(0.f, 0.f, 0.f, 0.f);
    if (tid < 256 && blockIdx.x < NG8)
        zv = *(const float4*)&z_flat[(size_t)(blockIdx.x * 8 + row4) * 128 + c4];
    for (int g = blockIdx.x; g < NG8; g += GRID_G) {
        if (tid < 256) {
            float zx = fminf(fmaxf(zv.x, -1e6f), 1e6f);
            float zy = fminf(fmaxf(zv.y, -1e6f), 1e6f);
            float zz = fminf(fmaxf(zv.z, -1e6f), 1e6f);
            float zw = fminf(fmaxf(zv.w, -1e6f), 1e6f);
            float4 w = make_float4((zx - zm4.x) * zi4.x, (zy - zm4.y) * zi4.y,
                                   (zz - zm4.z) * zi4.z, (zw - zm4.w) * zi4.w);
            *(float4*)&s_zn[row4][c4] = w;
            if (zpk) { s_zp[row4][node2] = zx; s_zp[row4][node2 + 1] = zy; }
        }
        __syncthreads();
        int gn = g + GRID_G;
        float4 zv_n = make_float4(0.f, 0.f, 0.f, 0.f);
        if (tid < 256 && gn < NG8)
            zv_n = *(const float4*)&z_flat[(size_t)(gn * 8 + row4) * 128 + c4];
        if (tid < 480) {
            s_d[br][bp]     = pbc_dist(s_zp[br], bi, bj);
            s_d[br + 4][bp] = pbc_dist(s_zp[br + 4], bi, bj);
        }
        __syncthreads();
        switch (kind) {
            case 0: GROWS(s_zn[r][a]); break;
            case 1: GROWS(s_zn[r][a] * s_zn[r][a]); break;
            case 2: GROWS(__sinf(s_zn[r][a])); break;
            case 3: GROWS(__cosf(s_zn[r][a])); break;
            case 4: GROWS(__logf(fabsf(s_zn[r][a]) + 1e-3f)); break;
            case 5: GROWS(__expf(fminf(fmaxf(s_zn[r][a], -10.0f), 2.0f))); break;
            case 6:
                #pragma unroll
                for (int r = 0; r < 8; r++) {
                    float s = 0.0f;
                    #pragma unroll
                    for (int k = 4; k < 8; k++) { float t = s_zn[r][a + k]; s += t * t; }
                    GPOST(r, s);
                }
                break;
            case 7: GROWS(s_zn[r][a] * s_zn[r][b]); break;
            case 16: GROWS(CLIP6(s_d[r][a])); break;
            case 17: GROWS(CLIP6(frcp(s_d[r][a] + 1e-3f))); break;
            case 18: GROWS(CLIP6(frcp(s_d[r][a] * s_d[r][a] + 1e-3f))); break;
            case 19:
                #pragma unroll
                for (int r = 0; r < 8; r++) {
                    float dd = s_d[r][a]; float d2 = dd * dd;
                    GPOST(r, CLIP6(frcp(d2 * dd + 1e-3f)));
                }
                break;
            case 20:
                #pragma unroll
                for (int r = 0; r < 8; r++) {
                    float dd = s_d[r][a]; float d2 = dd * dd;
                    GPOST(r, CLIP6(frcp(d2 * d2 + 1e-3f)));
                }
                break;
            case 21:
                #pragma unroll
                for (int r = 0; r < 8; r++) {
                    float dd = s_d[r][a]; float d2 = dd * dd;
                    GPOST(r, CLIP6(frcp(d2 * d2 * dd + 1e-3f)));
                }
                break;
            case 22:
                #pragma unroll
                for (int r = 0; r < 8; r++) {
                    float dd = s_d[r][a]; float d2 = dd * dd; float d4 = d2 * d2;
                    GPOST(r, CLIP6(frcp(d4 * d2 + 1e-3f)));
                }
                break;
            case 23:
                #pragma unroll
                for (int r = 0; r < 8; r++) {
                    float dd = s_d[r][a]; float d2 = dd * dd; float d4 = d2 * d2;
                    GPOST(r, CLIP6(frcp(d4 * d4 + 1e-3f)));
                }
                break;
            case 24:
                #pragma unroll
                for (int r = 0; r < 8; r++) {
                    float dd = s_d[r][a]; float d2 = dd * dd; float d4 = d2 * d2;
                    GPOST(r, CLIP6(frcp(d4 * d4 * d2 + 1e-3f)));
                }
                break;
            case 25:
                #pragma unroll
                for (int r = 0; r < 8; r++) {
                    float dd = s_d[r][a]; float d2 = dd * dd; float d4 = d2 * d2;
                    GPOST(r, CLIP6(frcp(d4 * d4 * d4 + 1e-3f)));
                }
                break;
            case 26:
                #pragma unroll
                for (int r = 0; r < 8; r++) {
                    float dd = s_d[r][a]; float d2 = dd * dd; float d4 = d2 * d2;
                    float d8 = d4 * d4;
                    GPOST(r, CLIP6(frcp(d8 * d4 * d2 + 1e-3f)));
                }
                break;
            case 27: GROWS(CLIP6(__expf(-s_d[r][a]))); break;
            case 28:
                #pragma unroll
                for (int r = 0; r < 8; r++) {
                    float dd = s_d[r][a];
                    GPOST(r, CLIP6(__expf(-dd) * frcp(dd + 1e-3f)));
                }
                break;
            default: GROWS(CLIP6(__logf(s_d[r][a] + 1e-3f))); break;
        }
        __syncthreads();
        #pragma unroll
        for (int w = 0; w < 2; w++) {
            int f = tid + w * 512;            // float4 index within 8x512 tile
            int r = f >> 7, cc = f & 127;
            float4 wv = *(const float4*)&s_out[r][cc * 4];
            *(float4*)&out[(size_t)(g * 8 + r) * 512 + cc * 4] = wv;
        }
        zv = zv_n;
    }
}

extern "C" void kernel_launch(void* const* d_in, const int* in_sizes, int n_in,
                              void* d_out, int out_size) {
    const float* z_flat      = (const float*)d_in[0];
    const float* z_mean      = (const float*)d_in[1];
    const float* z_std       = (const float*)d_in[2];
    const float* x_poly_mean = (const float*)d_in[3];
    const float* x_poly_std  = (const float*)d_in[4];
    const int*   feature_mask = (const int*)d_in[5];
    float* out = (float*)d_out;

    p1dist_kernel<<<GRID_P, 512>>>(z_flat);
    p1rest_kernel<<<GRID_P, 512>>>(z_flat, z_mean, z_std);
    select_kernel<<<SEL_NB, 1024>>>(feature_mask);
    gather_kernel<<<GRID_G, 512>>>(z_flat, z_mean, z_std,
                                   x_poly_mean, x_poly_std, feature_mask, out);
}